// round 1
// baseline (speedup 1.0000x reference)
#include <cuda_runtime.h>
#include <math.h>

#define B  32
#define LX 64
#define TT 64
#define D  1024
#define V  32000

// ------------------- scratch (static device globals; no allocation) ---------
__device__ float g_h[B * D];
__device__ float g_c[B * D];
__device__ float g_feed[B * 2 * D];            // ctx / input_feed
__device__ float g_gatesp[2][B * 4 * D];       // split-K partials for gates
__device__ float g_hprojp[4][B * D];           // split-K partials for hproj
__device__ float g_prep[4][B * D];             // split-K partials for pre-readout
__device__ float g_attw[B * LX];               // raw attention scores
__device__ float g_pre[TT * B * D];            // tanh(pre) for all steps [T,B,D]

// ------------------- init ---------------------------------------------------
__global__ void k_init0(const float* __restrict__ h0, const float* __restrict__ c0) {
    int i = blockIdx.x * blockDim.x + threadIdx.x;
    if (i < B * D) { g_h[i] = h0[i]; g_c[i] = c0[i]; }
    if (i < B * 2 * D) g_feed[i] = 0.f;
}

// ------------------- gates GEMM: [32,4096] = x[32,4096k] * W^T --------------
// x = concat(emb(y_t), input_feed, h_prev); W = [W_ih | W_hh] per column j.
// tile 32 rows x 64 cols, 256 thr, KC=32, grid.x=64 col-tiles, grid.y=2 ksplit
__global__ void __launch_bounds__(256) k_gates(
    const float* __restrict__ word_emb, const int* __restrict__ y_train,
    const float* __restrict__ W_ih, const float* __restrict__ W_hh, int t) {
    __shared__ float xs[32][34];
    __shared__ float ws[32][68];
    __shared__ int yidx[B];
    int tid = threadIdx.x;
    int j0 = blockIdx.x * 64;
    int kbeg = blockIdx.y * 2048;
    int cx = tid & 15, ty = tid >> 4;     // compute: cols 4cx.., rows 2ty..
    int lr = tid & 31, lkq = tid >> 5;    // xs load
    int lj = tid & 63, lwq = tid >> 6;    // ws load
    if (tid < B) yidx[tid] = y_train[tid * TT + t];
    __syncthreads();
    float acc[2][4] = {};
    for (int k0 = kbeg; k0 < kbeg + 2048; k0 += 32) {
        { // xs[kk][row] (transposed)
            int k = k0 + lkq * 4;
            const float* src;
            if (k < D)            src = word_emb + (size_t)yidx[lr] * D + k;
            else if (k < 3 * D)   src = g_feed + lr * 2 * D + (k - D);
            else                  src = g_h + lr * D + (k - 3 * D);
            float4 v = *(const float4*)src;
            xs[lkq*4+0][lr] = v.x; xs[lkq*4+1][lr] = v.y;
            xs[lkq*4+2][lr] = v.z; xs[lkq*4+3][lr] = v.w;
        }
        { // ws[kk][col] (transposed)
            int k = k0 + lwq * 8;
            const float* wsrc;
            if (k < 3 * D) wsrc = W_ih + (size_t)(j0 + lj) * (3 * D) + k;
            else           wsrc = W_hh + (size_t)(j0 + lj) * D + (k - 3 * D);
            float4 v0 = *(const float4*)wsrc;
            float4 v1 = *(const float4*)(wsrc + 4);
            ws[lwq*8+0][lj] = v0.x; ws[lwq*8+1][lj] = v0.y;
            ws[lwq*8+2][lj] = v0.z; ws[lwq*8+3][lj] = v0.w;
            ws[lwq*8+4][lj] = v1.x; ws[lwq*8+5][lj] = v1.y;
            ws[lwq*8+6][lj] = v1.z; ws[lwq*8+7][lj] = v1.w;
        }
        __syncthreads();
#pragma unroll
        for (int kk = 0; kk < 32; kk++) {
            float2 a = *(const float2*)&xs[kk][2 * ty];
            float4 w = *(const float4*)&ws[kk][4 * cx];
            acc[0][0] += a.x * w.x; acc[0][1] += a.x * w.y;
            acc[0][2] += a.x * w.z; acc[0][3] += a.x * w.w;
            acc[1][0] += a.y * w.x; acc[1][1] += a.y * w.y;
            acc[1][2] += a.y * w.z; acc[1][3] += a.y * w.w;
        }
        __syncthreads();
    }
    int s = blockIdx.y;
    *(float4*)&g_gatesp[s][(2*ty+0) * (4*D) + j0 + 4*cx] =
        make_float4(acc[0][0], acc[0][1], acc[0][2], acc[0][3]);
    *(float4*)&g_gatesp[s][(2*ty+1) * (4*D) + j0 + 4*cx] =
        make_float4(acc[1][0], acc[1][1], acc[1][2], acc[1][3]);
}

// ------------------- LSTM cell (sums gate partials + biases) ----------------
__global__ void k_cell(const float* __restrict__ b_ih, const float* __restrict__ b_hh) {
    int i = blockIdx.x * blockDim.x + threadIdx.x;     // < B*D
    int b = i >> 10, d = i & 1023;
    const float* g0 = g_gatesp[0] + b * 4 * D;
    const float* g1 = g_gatesp[1] + b * 4 * D;
    float ig = g0[d]        + g1[d]        + b_ih[d]        + b_hh[d];
    float fg = g0[D + d]    + g1[D + d]    + b_ih[D + d]    + b_hh[D + d];
    float gg = g0[2*D + d]  + g1[2*D + d]  + b_ih[2*D + d]  + b_hh[2*D + d];
    float og = g0[3*D + d]  + g1[3*D + d]  + b_ih[3*D + d]  + b_hh[3*D + d];
    float si = 1.f / (1.f + expf(-ig));
    float sf = 1.f / (1.f + expf(-fg));
    float so = 1.f / (1.f + expf(-og));
    float c = sf * g_c[i] + si * tanhf(gg);
    g_c[i] = c;
    g_h[i] = so * tanhf(c);
}

// ------------------- hproj GEMM: [32,1024] = h * w_trg_W^T ------------------
__global__ void __launch_bounds__(256) k_hproj(const float* __restrict__ Wt) {
    __shared__ float xs[32][34];
    __shared__ float ws[32][68];
    int tid = threadIdx.x;
    int j0 = blockIdx.x * 64;
    int kbeg = blockIdx.y * 256;
    int cx = tid & 15, ty = tid >> 4;
    int lr = tid & 31, lkq = tid >> 5;
    int lj = tid & 63, lwq = tid >> 6;
    float acc[2][4] = {};
    for (int k0 = kbeg; k0 < kbeg + 256; k0 += 32) {
        {
            float4 v = *(const float4*)(g_h + lr * D + k0 + lkq * 4);
            xs[lkq*4+0][lr] = v.x; xs[lkq*4+1][lr] = v.y;
            xs[lkq*4+2][lr] = v.z; xs[lkq*4+3][lr] = v.w;
        }
        {
            const float* wsrc = Wt + (size_t)(j0 + lj) * D + k0 + lwq * 8;
            float4 v0 = *(const float4*)wsrc;
            float4 v1 = *(const float4*)(wsrc + 4);
            ws[lwq*8+0][lj] = v0.x; ws[lwq*8+1][lj] = v0.y;
            ws[lwq*8+2][lj] = v0.z; ws[lwq*8+3][lj] = v0.w;
            ws[lwq*8+4][lj] = v1.x; ws[lwq*8+5][lj] = v1.y;
            ws[lwq*8+6][lj] = v1.z; ws[lwq*8+7][lj] = v1.w;
        }
        __syncthreads();
#pragma unroll
        for (int kk = 0; kk < 32; kk++) {
            float2 a = *(const float2*)&xs[kk][2 * ty];
            float4 w = *(const float4*)&ws[kk][4 * cx];
            acc[0][0] += a.x * w.x; acc[0][1] += a.x * w.y;
            acc[0][2] += a.x * w.z; acc[0][3] += a.x * w.w;
            acc[1][0] += a.y * w.x; acc[1][1] += a.y * w.y;
            acc[1][2] += a.y * w.z; acc[1][3] += a.y * w.w;
        }
        __syncthreads();
    }
    int s = blockIdx.y;
    *(float4*)&g_hprojp[s][(2*ty+0) * D + j0 + 4*cx] =
        make_float4(acc[0][0], acc[0][1], acc[0][2], acc[0][3]);
    *(float4*)&g_hprojp[s][(2*ty+1) * D + j0 + 4*cx] =
        make_float4(acc[1][0], acc[1][1], acc[1][2], acc[1][3]);
}

// ------------------- attention scores ---------------------------------------
__global__ void k_scores(const float* __restrict__ x_enc_k,
                         const unsigned char* __restrict__ x_mask,
                         const float* __restrict__ w_att,
                         const float* __restrict__ w_att_b,
                         const float* __restrict__ w_trg_b) {
    int bl = blockIdx.x;                // b*64 + l
    int b = bl >> 6;
    int tid = threadIdx.x;              // 128 threads
    const float* xk = x_enc_k + (size_t)bl * D;
    float s = 0.f;
#pragma unroll
    for (int i = 0; i < 8; i++) {
        int d = tid + i * 128;
        float hp = g_hprojp[0][b * D + d] + g_hprojp[1][b * D + d]
                 + g_hprojp[2][b * D + d] + g_hprojp[3][b * D + d]
                 + w_trg_b[d];
        s += tanhf(xk[d] + hp) * w_att[d];
    }
#pragma unroll
    for (int off = 16; off; off >>= 1) s += __shfl_xor_sync(0xffffffffu, s, off);
    __shared__ float red[4];
    if ((tid & 31) == 0) red[tid >> 5] = s;
    __syncthreads();
    if (tid == 0) {
        float tot = red[0] + red[1] + red[2] + red[3] + w_att_b[0];
        if (x_mask[bl]) tot = -1e9f;
        g_attw[bl] = tot;
    }
}

// ------------------- softmax + ctx (writes next input_feed) -----------------
__global__ void k_ctx(const float* __restrict__ x_enc) {
    int b = blockIdx.x >> 3;
    int part = blockIdx.x & 7;
    int tid = threadIdx.x;              // 256 threads
    __shared__ float w[LX];
    if (tid == 0) {
        float mx = -1e30f;
        for (int l = 0; l < LX; l++) mx = fmaxf(mx, g_attw[b * LX + l]);
        float z = 0.f;
        for (int l = 0; l < LX; l++) { float e = expf(g_attw[b * LX + l] - mx); w[l] = e; z += e; }
        float inv = 1.f / z;
        for (int l = 0; l < LX; l++) w[l] *= inv;
    }
    __syncthreads();
    int d2 = part * 256 + tid;
    const float* xe = x_enc + (size_t)b * LX * 2 * D + d2;
    float acc = 0.f;
#pragma unroll 8
    for (int l = 0; l < LX; l++) acc += w[l] * xe[(size_t)l * 2 * D];
    g_feed[b * 2 * D + d2] = acc;
}

// ------------------- pre GEMM: [32,1024] = [h|ctx] * ctx_W^T ----------------
__global__ void __launch_bounds__(256) k_pre(const float* __restrict__ Cw) {
    __shared__ float xs[32][34];
    __shared__ float ws[32][68];
    int tid = threadIdx.x;
    int j0 = blockIdx.x * 64;
    int kbeg = blockIdx.y * 768;
    int cx = tid & 15, ty = tid >> 4;
    int lr = tid & 31, lkq = tid >> 5;
    int lj = tid & 63, lwq = tid >> 6;
    float acc[2][4] = {};
    for (int k0 = kbeg; k0 < kbeg + 768; k0 += 32) {
        {
            int k = k0 + lkq * 4;
            const float* src = (k < D) ? (g_h + lr * D + k)
                                       : (g_feed + lr * 2 * D + (k - D));
            float4 v = *(const float4*)src;
            xs[lkq*4+0][lr] = v.x; xs[lkq*4+1][lr] = v.y;
            xs[lkq*4+2][lr] = v.z; xs[lkq*4+3][lr] = v.w;
        }
        {
            const float* wsrc = Cw + (size_t)(j0 + lj) * (3 * D) + k0 + lwq * 8;
            float4 v0 = *(const float4*)wsrc;
            float4 v1 = *(const float4*)(wsrc + 4);
            ws[lwq*8+0][lj] = v0.x; ws[lwq*8+1][lj] = v0.y;
            ws[lwq*8+2][lj] = v0.z; ws[lwq*8+3][lj] = v0.w;
            ws[lwq*8+4][lj] = v1.x; ws[lwq*8+5][lj] = v1.y;
            ws[lwq*8+6][lj] = v1.z; ws[lwq*8+7][lj] = v1.w;
        }
        __syncthreads();
#pragma unroll
        for (int kk = 0; kk < 32; kk++) {
            float2 a = *(const float2*)&xs[kk][2 * ty];
            float4 w = *(const float4*)&ws[kk][4 * cx];
            acc[0][0] += a.x * w.x; acc[0][1] += a.x * w.y;
            acc[0][2] += a.x * w.z; acc[0][3] += a.x * w.w;
            acc[1][0] += a.y * w.x; acc[1][1] += a.y * w.y;
            acc[1][2] += a.y * w.z; acc[1][3] += a.y * w.w;
        }
        __syncthreads();
    }
    int s = blockIdx.y;
    *(float4*)&g_prep[s][(2*ty+0) * D + j0 + 4*cx] =
        make_float4(acc[0][0], acc[0][1], acc[0][2], acc[0][3]);
    *(float4*)&g_prep[s][(2*ty+1) * D + j0 + 4*cx] =
        make_float4(acc[1][0], acc[1][1], acc[1][2], acc[1][3]);
}

// ------------------- finish pre: sum partials + tanh -> g_pre[t] ------------
__global__ void k_pretanh(int t) {
    int i = blockIdx.x * blockDim.x + threadIdx.x;     // < B*D
    float v = g_prep[0][i] + g_prep[1][i] + g_prep[2][i] + g_prep[3][i];
    g_pre[(size_t)t * B * D + i] = tanhf(v);
}

// ------------------- logits GEMM: [2048,32000] = pre * readout_W^T ----------
// tile 128x128, 256 thr, 8x8 micro, KC=16
__global__ void __launch_bounds__(256) k_logits(const float* __restrict__ RW,
                                                float* __restrict__ out) {
    __shared__ float as[16][132];
    __shared__ float bs[16][132];
    int tid = threadIdx.x;
    int row0 = blockIdx.y << 7;
    int col0 = blockIdx.x << 7;
    int lr = tid & 127, lq = tid >> 7;
    int cx = tid & 15, ry = tid >> 4;
    float acc[8][8];
#pragma unroll
    for (int i = 0; i < 8; i++)
#pragma unroll
        for (int j = 0; j < 8; j++) acc[i][j] = 0.f;

    for (int k0 = 0; k0 < D; k0 += 16) {
        const float* pa = g_pre + (size_t)(row0 + lr) * D + k0 + lq * 8;
        float4 a0 = *(const float4*)pa, a1 = *(const float4*)(pa + 4);
        const float* pb = RW + (size_t)(col0 + lr) * D + k0 + lq * 8;
        float4 b0 = *(const float4*)pb, b1 = *(const float4*)(pb + 4);
        as[lq*8+0][lr] = a0.x; as[lq*8+1][lr] = a0.y; as[lq*8+2][lr] = a0.z; as[lq*8+3][lr] = a0.w;
        as[lq*8+4][lr] = a1.x; as[lq*8+5][lr] = a1.y; as[lq*8+6][lr] = a1.z; as[lq*8+7][lr] = a1.w;
        bs[lq*8+0][lr] = b0.x; bs[lq*8+1][lr] = b0.y; bs[lq*8+2][lr] = b0.z; bs[lq*8+3][lr] = b0.w;
        bs[lq*8+4][lr] = b1.x; bs[lq*8+5][lr] = b1.y; bs[lq*8+6][lr] = b1.z; bs[lq*8+7][lr] = b1.w;
        __syncthreads();
#pragma unroll
        for (int kk = 0; kk < 16; kk++) {
            float4 x0 = *(const float4*)&as[kk][ry * 8];
            float4 x1 = *(const float4*)&as[kk][ry * 8 + 4];
            float4 y0 = *(const float4*)&bs[kk][cx * 8];
            float4 y1 = *(const float4*)&bs[kk][cx * 8 + 4];
            float a[8] = {x0.x, x0.y, x0.z, x0.w, x1.x, x1.y, x1.z, x1.w};
            float w[8] = {y0.x, y0.y, y0.z, y0.w, y1.x, y1.y, y1.z, y1.w};
#pragma unroll
            for (int i = 0; i < 8; i++)
#pragma unroll
                for (int j = 0; j < 8; j++) acc[i][j] += a[i] * w[j];
        }
        __syncthreads();
    }
#pragma unroll
    for (int i = 0; i < 8; i++) {
        int m = row0 + ry * 8 + i;          // m = t*B + b
        int bb = m & 31, t = m >> 5;
        float* o = out + ((size_t)bb * TT + t) * V + col0 + cx * 8;
        *(float4*)o       = make_float4(acc[i][0], acc[i][1], acc[i][2], acc[i][3]);
        *(float4*)(o + 4) = make_float4(acc[i][4], acc[i][5], acc[i][6], acc[i][7]);
    }
}

// ------------------- launch -------------------------------------------------
extern "C" void kernel_launch(void* const* d_in, const int* in_sizes, int n_in,
                              void* d_out, int out_size) {
    const float* x_enc      = (const float*)d_in[0];
    const float* x_enc_k    = (const float*)d_in[1];
    const float* h0         = (const float*)d_in[2];
    const float* c0         = (const float*)d_in[3];
    const unsigned char* xm = (const unsigned char*)d_in[4];
    const int*   y_train    = (const int*)d_in[5];
    const float* word_emb   = (const float*)d_in[6];
    const float* W_ih       = (const float*)d_in[7];
    const float* W_hh       = (const float*)d_in[8];
    const float* b_ih       = (const float*)d_in[9];
    const float* b_hh       = (const float*)d_in[10];
    const float* w_trg_W    = (const float*)d_in[11];
    const float* w_trg_b    = (const float*)d_in[12];
    const float* w_att      = (const float*)d_in[13];
    const float* w_att_b    = (const float*)d_in[14];
    const float* ctx_W      = (const float*)d_in[15];
    const float* RW         = (const float*)d_in[16];
    float* out = (float*)d_out;

    k_init0<<<(B * 2 * D + 255) / 256, 256>>>(h0, c0);
    for (int t = 0; t < TT; t++) {
        k_gates<<<dim3(64, 2), 256>>>(word_emb, y_train, W_ih, W_hh, t);
        k_cell<<<B * D / 256, 256>>>(b_ih, b_hh);
        k_hproj<<<dim3(16, 4), 256>>>(w_trg_W);
        k_scores<<<B * LX, 128>>>(x_enc_k, xm, w_att, w_att_b, w_trg_b);
        k_ctx<<<B * 8, 256>>>(x_enc);
        k_pre<<<dim3(16, 4), 256>>>(ctx_W);
        k_pretanh<<<B * D / 256, 256>>>(t);
    }
    k_logits<<<dim3(V / 128, (B * TT) / 128), 256>>>(RW, out);
}

// round 2
// speedup vs baseline: 1.0137x; 1.0137x over previous
#include <cuda_runtime.h>
#include <math.h>

#define B  32
#define LX 64
#define TT 64
#define D  1024
#define V  32000

// ------------------- scratch -------------------------------------------------
__device__ float g_h[B * D];
__device__ float g_c[B * D];
__device__ float g_feed[B * 2 * D];
__device__ float g_gatesp[4][B * 4 * D];       // split-K partials (gates)
__device__ float g_hprojp[16][B * D];          // split-K partials (hproj)
__device__ float g_prep[16][B * D];            // split-K partials (pre)
__device__ float g_pre[TT * B * D];            // tanh(pre) [T*B, D]

// ------------------- f32x2 helpers -------------------------------------------
__device__ __forceinline__ unsigned long long dup2(float x) {
    unsigned long long r;
    asm("mov.b64 %0, {%1, %1};" : "=l"(r) : "f"(x));
    return r;
}
__device__ __forceinline__ void ffma2(unsigned long long& d,
                                      unsigned long long a, unsigned long long b) {
    asm("fma.rn.f32x2 %0, %1, %2, %0;" : "+l"(d) : "l"(a), "l"(b));
}
__device__ __forceinline__ float fast_tanh(float x) {
    float e = __expf(2.f * x);
    return 1.f - __fdividef(2.f, e + 1.f);
}

// ------------------- init ----------------------------------------------------
__global__ void k_init0(const float* __restrict__ h0, const float* __restrict__ c0) {
    int i = blockIdx.x * blockDim.x + threadIdx.x;
    if (i < B * D) { g_h[i] = h0[i]; g_c[i] = c0[i]; }
    if (i < B * 2 * D) g_feed[i] = 0.f;
}

// ------------------- gates GEMM: [32,4096] = x[32,4096] * Wcat^T --------------
// tile 32x128, 256 thr, micro 2x8 via f32x2, grid (32 coltiles, 4 ksplit)
__global__ void __launch_bounds__(256) k_gates(
    const float* __restrict__ word_emb, const int* __restrict__ y_train,
    const float* __restrict__ W_ih, const float* __restrict__ W_hh, int t) {
    __shared__ __align__(16) float xs[32][34];    // xs[kk][row]
    __shared__ __align__(16) float ws[32][132];   // ws[kk][col]
    __shared__ int yidx[B];
    int tid = threadIdx.x;
    int s  = blockIdx.y;
    int j0 = blockIdx.x * 128;
    int cx = tid & 15, ty = tid >> 4;     // compute: cols 8cx.., rows 2ty..
    int lr = tid & 31, lkq = tid >> 5;    // xs loader
    int lc = tid & 127, lh = tid >> 7;    // ws loader
    if (tid < B) yidx[tid] = y_train[tid * TT + t];
    __syncthreads();

    unsigned long long acc[2][4] = {};
    for (int kt = 0; kt < 32; kt++) {
        { // xs: 32 rows x 32 k
            int kg = kt * 32 + lkq * 4;   // local k within split
            const float* px;
            if (s == 0)      px = word_emb + (size_t)yidx[lr] * D + kg;
            else if (s == 1) px = g_feed + lr * 2 * D + kg;
            else if (s == 2) px = g_feed + lr * 2 * D + 1024 + kg;
            else             px = g_h + lr * D + kg;
            float4 v = *(const float4*)px;
            xs[lkq*4+0][lr] = v.x; xs[lkq*4+1][lr] = v.y;
            xs[lkq*4+2][lr] = v.z; xs[lkq*4+3][lr] = v.w;
        }
        { // ws: 32 k x 128 cols
            int kg = kt * 32 + lh * 16;
            const float* pw = (s < 3)
                ? W_ih + (size_t)(j0 + lc) * (3 * D) + s * 1024 + kg
                : W_hh + (size_t)(j0 + lc) * D + kg;
#pragma unroll
            for (int m = 0; m < 4; m++) {
                float4 v = *(const float4*)(pw + m * 4);
                int k = lh * 16 + m * 4;
                ws[k+0][lc] = v.x; ws[k+1][lc] = v.y;
                ws[k+2][lc] = v.z; ws[k+3][lc] = v.w;
            }
        }
        __syncthreads();
#pragma unroll
        for (int kk = 0; kk < 32; kk++) {
            float2 a = *(const float2*)&xs[kk][2 * ty];
            unsigned long long ax = dup2(a.x), ay = dup2(a.y);
            const ulonglong2* wp = (const ulonglong2*)&ws[kk][8 * cx];
            ulonglong2 w01 = wp[0], w23 = wp[1];
            ffma2(acc[0][0], ax, w01.x); ffma2(acc[0][1], ax, w01.y);
            ffma2(acc[0][2], ax, w23.x); ffma2(acc[0][3], ax, w23.y);
            ffma2(acc[1][0], ay, w01.x); ffma2(acc[1][1], ay, w01.y);
            ffma2(acc[1][2], ay, w23.x); ffma2(acc[1][3], ay, w23.y);
        }
        __syncthreads();
    }
#pragma unroll
    for (int r = 0; r < 2; r++) {
        float* o = &g_gatesp[s][(2*ty + r) * (4*D) + j0 + 8*cx];
        ((ulonglong2*)o)[0] = make_ulonglong2(acc[r][0], acc[r][1]);
        ((ulonglong2*)o)[1] = make_ulonglong2(acc[r][2], acc[r][3]);
    }
}

// ------------------- LSTM cell ------------------------------------------------
__global__ void k_cell(const float* __restrict__ b_ih, const float* __restrict__ b_hh) {
    int i = blockIdx.x * blockDim.x + threadIdx.x;     // < B*D
    int b = i >> 10, d = i & 1023;
    float ig = b_ih[d]       + b_hh[d];
    float fg = b_ih[D+d]     + b_hh[D+d];
    float gg = b_ih[2*D+d]   + b_hh[2*D+d];
    float og = b_ih[3*D+d]   + b_hh[3*D+d];
#pragma unroll
    for (int s = 0; s < 4; s++) {
        const float* g = g_gatesp[s] + b * 4 * D;
        ig += g[d]; fg += g[D+d]; gg += g[2*D+d]; og += g[3*D+d];
    }
    float si = 1.f / (1.f + expf(-ig));
    float sf = 1.f / (1.f + expf(-fg));
    float so = 1.f / (1.f + expf(-og));
    float c = sf * g_c[i] + si * tanhf(gg);
    g_c[i] = c;
    g_h[i] = so * tanhf(c);
}

// ------------------- hproj GEMM: [32,1024] = h * w_trg_W^T ---------------------
// tile 32x128, grid (8 coltiles, 16 ksplit), K/split = 64
__global__ void __launch_bounds__(256) k_hproj(const float* __restrict__ Wt) {
    __shared__ __align__(16) float xs[32][34];
    __shared__ __align__(16) float ws[32][132];
    int tid = threadIdx.x;
    int s  = blockIdx.y;
    int j0 = blockIdx.x * 128;
    int cx = tid & 15, ty = tid >> 4;
    int lr = tid & 31, lkq = tid >> 5;
    int lc = tid & 127, lh = tid >> 7;

    unsigned long long acc[2][4] = {};
    for (int kt = 0; kt < 2; kt++) {
        int kbase = s * 64 + kt * 32;
        {
            float4 v = *(const float4*)(g_h + lr * D + kbase + lkq * 4);
            xs[lkq*4+0][lr] = v.x; xs[lkq*4+1][lr] = v.y;
            xs[lkq*4+2][lr] = v.z; xs[lkq*4+3][lr] = v.w;
        }
        {
            const float* pw = Wt + (size_t)(j0 + lc) * D + kbase + lh * 16;
#pragma unroll
            for (int m = 0; m < 4; m++) {
                float4 v = *(const float4*)(pw + m * 4);
                int k = lh * 16 + m * 4;
                ws[k+0][lc] = v.x; ws[k+1][lc] = v.y;
                ws[k+2][lc] = v.z; ws[k+3][lc] = v.w;
            }
        }
        __syncthreads();
#pragma unroll
        for (int kk = 0; kk < 32; kk++) {
            float2 a = *(const float2*)&xs[kk][2 * ty];
            unsigned long long ax = dup2(a.x), ay = dup2(a.y);
            const ulonglong2* wp = (const ulonglong2*)&ws[kk][8 * cx];
            ulonglong2 w01 = wp[0], w23 = wp[1];
            ffma2(acc[0][0], ax, w01.x); ffma2(acc[0][1], ax, w01.y);
            ffma2(acc[0][2], ax, w23.x); ffma2(acc[0][3], ax, w23.y);
            ffma2(acc[1][0], ay, w01.x); ffma2(acc[1][1], ay, w01.y);
            ffma2(acc[1][2], ay, w23.x); ffma2(acc[1][3], ay, w23.y);
        }
        __syncthreads();
    }
#pragma unroll
    for (int r = 0; r < 2; r++) {
        float* o = &g_hprojp[s][(2*ty + r) * D + j0 + 8*cx];
        ((ulonglong2*)o)[0] = make_ulonglong2(acc[r][0], acc[r][1]);
        ((ulonglong2*)o)[1] = make_ulonglong2(acc[r][2], acc[r][3]);
    }
}

// ------------------- fused attention: scores + softmax + ctx -------------------
// grid = B, 512 threads
__global__ void __launch_bounds__(512) k_attn(
    const float* __restrict__ x_enc, const float* __restrict__ x_enc_k,
    const unsigned char* __restrict__ x_mask,
    const float* __restrict__ w_att, const float* __restrict__ w_att_b,
    const float* __restrict__ w_trg_b) {
    __shared__ float hp[D];
    __shared__ float wl[LX];
    int b = blockIdx.x;
    int tid = threadIdx.x;
    int lane = tid & 31, wid = tid >> 5;

    // phase 1: finalize hproj partial sums
#pragma unroll
    for (int d = tid; d < D; d += 512) {
        float sum = w_trg_b[d];
#pragma unroll
        for (int s = 0; s < 16; s++) sum += g_hprojp[s][b * D + d];
        hp[d] = sum;
    }
    __syncthreads();

    // phase 2: scores (16 warps x 4 l each)
    for (int l = wid; l < LX; l += 16) {
        const float* xk = x_enc_k + (size_t)(b * LX + l) * D;
        float s = 0.f;
#pragma unroll 8
        for (int i = 0; i < 32; i++) {
            int d = lane + i * 32;
            s += fast_tanh(xk[d] + hp[d]) * w_att[d];
        }
#pragma unroll
        for (int off = 16; off; off >>= 1) s += __shfl_xor_sync(0xffffffffu, s, off);
        if (lane == 0) {
            float tot = s + w_att_b[0];
            if (x_mask[b * LX + l]) tot = -1e9f;
            wl[l] = tot;
        }
    }
    __syncthreads();

    // phase 3: softmax (serial, tiny)
    if (tid == 0) {
        float mx = -1e30f;
        for (int l = 0; l < LX; l++) mx = fmaxf(mx, wl[l]);
        float z = 0.f;
        for (int l = 0; l < LX; l++) { float e = expf(wl[l] - mx); wl[l] = e; z += e; }
        float inv = 1.f / z;
        for (int l = 0; l < LX; l++) wl[l] *= inv;
    }
    __syncthreads();

    // phase 4: ctx -> g_feed
    {
        int d2 = tid * 4;
        const float4* xe = (const float4*)(x_enc + (size_t)b * LX * 2 * D + d2);
        float4 acc = make_float4(0.f, 0.f, 0.f, 0.f);
#pragma unroll 8
        for (int l = 0; l < LX; l++) {
            float w = wl[l];
            float4 xv = xe[(size_t)l * (2 * D / 4)];
            acc.x += w * xv.x; acc.y += w * xv.y;
            acc.z += w * xv.z; acc.w += w * xv.w;
        }
        *(float4*)&g_feed[b * 2 * D + d2] = acc;
    }
}

// ------------------- pre GEMM: [32,1024] = [h|ctx] * ctx_W^T -------------------
// tile 32x128, grid (8 coltiles, 16 ksplit), K/split = 192
__global__ void __launch_bounds__(256) k_pre(const float* __restrict__ Cw) {
    __shared__ __align__(16) float xs[32][34];
    __shared__ __align__(16) float ws[32][132];
    int tid = threadIdx.x;
    int s  = blockIdx.y;
    int j0 = blockIdx.x * 128;
    int cx = tid & 15, ty = tid >> 4;
    int lr = tid & 31, lkq = tid >> 5;
    int lc = tid & 127, lh = tid >> 7;

    unsigned long long acc[2][4] = {};
    for (int kt = 0; kt < 6; kt++) {
        int kbase = s * 192 + kt * 32;       // global k in [0, 3072)
        {
            int k = kbase + lkq * 4;
            const float* px = (k < D) ? (g_h + lr * D + k)
                                      : (g_feed + lr * 2 * D + (k - D));
            float4 v = *(const float4*)px;
            xs[lkq*4+0][lr] = v.x; xs[lkq*4+1][lr] = v.y;
            xs[lkq*4+2][lr] = v.z; xs[lkq*4+3][lr] = v.w;
        }
        {
            const float* pw = Cw + (size_t)(j0 + lc) * (3 * D) + kbase + lh * 16;
#pragma unroll
            for (int m = 0; m < 4; m++) {
                float4 v = *(const float4*)(pw + m * 4);
                int k = lh * 16 + m * 4;
                ws[k+0][lc] = v.x; ws[k+1][lc] = v.y;
                ws[k+2][lc] = v.z; ws[k+3][lc] = v.w;
            }
        }
        __syncthreads();
#pragma unroll
        for (int kk = 0; kk < 32; kk++) {
            float2 a = *(const float2*)&xs[kk][2 * ty];
            unsigned long long ax = dup2(a.x), ay = dup2(a.y);
            const ulonglong2* wp = (const ulonglong2*)&ws[kk][8 * cx];
            ulonglong2 w01 = wp[0], w23 = wp[1];
            ffma2(acc[0][0], ax, w01.x); ffma2(acc[0][1], ax, w01.y);
            ffma2(acc[0][2], ax, w23.x); ffma2(acc[0][3], ax, w23.y);
            ffma2(acc[1][0], ay, w01.x); ffma2(acc[1][1], ay, w01.y);
            ffma2(acc[1][2], ay, w23.x); ffma2(acc[1][3], ay, w23.y);
        }
        __syncthreads();
    }
#pragma unroll
    for (int r = 0; r < 2; r++) {
        float* o = &g_prep[s][(2*ty + r) * D + j0 + 8*cx];
        ((ulonglong2*)o)[0] = make_ulonglong2(acc[r][0], acc[r][1]);
        ((ulonglong2*)o)[1] = make_ulonglong2(acc[r][2], acc[r][3]);
    }
}

// ------------------- finish pre: sum partials + tanh -> g_pre[t] ---------------
__global__ void k_pretanh(int t) {
    int i = blockIdx.x * blockDim.x + threadIdx.x;     // < B*D
    float v = 0.f;
#pragma unroll
    for (int s = 0; s < 16; s++) v += g_prep[s][i];
    g_pre[(size_t)t * B * D + i] = tanhf(v);
}

// ------------------- logits GEMM: [2048,32000] = pre * readout_W^T -------------
// tile 128x128, 256 thr, 8x8 micro via f32x2, KC=16
__global__ void __launch_bounds__(256, 2) k_logits(const float* __restrict__ RW,
                                                   float* __restrict__ out) {
    __shared__ __align__(16) float as[16][132];
    __shared__ __align__(16) float bs[16][132];
    int tid = threadIdx.x;
    int row0 = blockIdx.y << 7;
    int col0 = blockIdx.x << 7;
    int lr = tid & 127, lq = tid >> 7;
    int cx = tid & 15, ry = tid >> 4;
    unsigned long long acc[8][4] = {};

    for (int k0 = 0; k0 < D; k0 += 16) {
        const float* pa = g_pre + (size_t)(row0 + lr) * D + k0 + lq * 8;
        float4 a0 = *(const float4*)pa, a1 = *(const float4*)(pa + 4);
        const float* pb = RW + (size_t)(col0 + lr) * D + k0 + lq * 8;
        float4 b0 = *(const float4*)pb, b1 = *(const float4*)(pb + 4);
        as[lq*8+0][lr] = a0.x; as[lq*8+1][lr] = a0.y; as[lq*8+2][lr] = a0.z; as[lq*8+3][lr] = a0.w;
        as[lq*8+4][lr] = a1.x; as[lq*8+5][lr] = a1.y; as[lq*8+6][lr] = a1.z; as[lq*8+7][lr] = a1.w;
        bs[lq*8+0][lr] = b0.x; bs[lq*8+1][lr] = b0.y; bs[lq*8+2][lr] = b0.z; bs[lq*8+3][lr] = b0.w;
        bs[lq*8+4][lr] = b1.x; bs[lq*8+5][lr] = b1.y; bs[lq*8+6][lr] = b1.z; bs[lq*8+7][lr] = b1.w;
        __syncthreads();
#pragma unroll
        for (int kk = 0; kk < 16; kk++) {
            float4 x0 = *(const float4*)&as[kk][ry * 8];
            float4 x1 = *(const float4*)&as[kk][ry * 8 + 4];
            const ulonglong2* wp = (const ulonglong2*)&bs[kk][cx * 8];
            ulonglong2 w01 = wp[0], w23 = wp[1];
            unsigned long long ad[8];
            ad[0] = dup2(x0.x); ad[1] = dup2(x0.y); ad[2] = dup2(x0.z); ad[3] = dup2(x0.w);
            ad[4] = dup2(x1.x); ad[5] = dup2(x1.y); ad[6] = dup2(x1.z); ad[7] = dup2(x1.w);
#pragma unroll
            for (int i = 0; i < 8; i++) {
                ffma2(acc[i][0], ad[i], w01.x);
                ffma2(acc[i][1], ad[i], w01.y);
                ffma2(acc[i][2], ad[i], w23.x);
                ffma2(acc[i][3], ad[i], w23.y);
            }
        }
        __syncthreads();
    }
#pragma unroll
    for (int i = 0; i < 8; i++) {
        int m = row0 + ry * 8 + i;          // m = t*B + b
        int bb = m & 31, t = m >> 5;
        float* o = out + ((size_t)bb * TT + t) * V + col0 + cx * 8;
        ((ulonglong2*)o)[0] = make_ulonglong2(acc[i][0], acc[i][1]);
        ((ulonglong2*)o)[1] = make_ulonglong2(acc[i][2], acc[i][3]);
    }
}

// ------------------- launch ----------------------------------------------------
extern "C" void kernel_launch(void* const* d_in, const int* in_sizes, int n_in,
                              void* d_out, int out_size) {
    const float* x_enc      = (const float*)d_in[0];
    const float* x_enc_k    = (const float*)d_in[1];
    const float* h0         = (const float*)d_in[2];
    const float* c0         = (const float*)d_in[3];
    const unsigned char* xm = (const unsigned char*)d_in[4];
    const int*   y_train    = (const int*)d_in[5];
    const float* word_emb   = (const float*)d_in[6];
    const float* W_ih       = (const float*)d_in[7];
    const float* W_hh       = (const float*)d_in[8];
    const float* b_ih       = (const float*)d_in[9];
    const float* b_hh       = (const float*)d_in[10];
    const float* w_trg_W    = (const float*)d_in[11];
    const float* w_trg_b    = (const float*)d_in[12];
    const float* w_att      = (const float*)d_in[13];
    const float* w_att_b    = (const float*)d_in[14];
    const float* ctx_W      = (const float*)d_in[15];
    const float* RW         = (const float*)d_in[16];
    float* out = (float*)d_out;

    k_init0<<<(B * 2 * D + 255) / 256, 256>>>(h0, c0);
    for (int t = 0; t < TT; t++) {
        k_gates<<<dim3(32, 4), 256>>>(word_emb, y_train, W_ih, W_hh, t);
        k_cell<<<B * D / 256, 256>>>(b_ih, b_hh);
        k_hproj<<<dim3(8, 16), 256>>>(w_trg_W);
        k_attn<<<B, 512>>>(x_enc, x_enc_k, xm, w_att, w_att_b, w_trg_b);
        k_pre<<<dim3(8, 16), 256>>>(ctx_W);
        k_pretanh<<<B * D / 256, 256>>>(t);
    }
    k_logits<<<dim3(V / 128, (B * TT) / 128), 256>>>(RW, out);
}

// round 4
// speedup vs baseline: 1.1582x; 1.1425x over previous
#include <cuda_runtime.h>
#include <cuda_bf16.h>
#include <math.h>
#include <stdint.h>

#define B  32
#define LX 64
#define TT 64
#define D  1024
#define V  32000
#define KP 3072          // K' for bf16 hi/lo GEMM: [hi|lo|hi] x [hi|hi|lo]

// ------------------- scratch -------------------------------------------------
__device__ float g_h[B * D];
__device__ float g_c[B * D];
__device__ float g_feed[B * 2 * D];
__device__ float g_gatesp[4][B * 4 * D];
__device__ float g_hprojp[16][B * D];
__device__ float g_prep[16][B * D];
__device__ __align__(16) __nv_bfloat16 g_Abf[(TT * B) * KP];   // [2048, 3072]
__device__ __align__(16) __nv_bfloat16 g_Bbf[V * KP];          // [32000,3072]

// ------------------- helpers --------------------------------------------------
__device__ __forceinline__ unsigned long long dup2(float x) {
    unsigned long long r;
    asm("mov.b64 %0, {%1, %1};" : "=l"(r) : "f"(x));
    return r;
}
__device__ __forceinline__ void ffma2(unsigned long long& d,
                                      unsigned long long a, unsigned long long b) {
    asm("fma.rn.f32x2 %0, %1, %2, %0;" : "+l"(d) : "l"(a), "l"(b));
}
__device__ __forceinline__ float fast_tanh(float x) {
    float e = __expf(2.f * x);
    return 1.f - __fdividef(2.f, e + 1.f);
}
__device__ __forceinline__ uint32_t smem_u32(const void* p) {
    uint32_t a;
    asm("{ .reg .u64 t; cvta.to.shared.u64 t, %1; cvt.u32.u64 %0, t; }" : "=r"(a) : "l"(p));
    return a;
}
__device__ __forceinline__ void cpasync16(uint32_t dst, const void* src) {
    asm volatile("cp.async.cg.shared.global [%0], [%1], 16;" :: "r"(dst), "l"(src));
}
__device__ __forceinline__ void ldm_x4(uint32_t* r, uint32_t addr) {
    asm volatile("ldmatrix.sync.aligned.m8n8.x4.shared.b16 {%0,%1,%2,%3}, [%4];"
        : "=r"(r[0]), "=r"(r[1]), "=r"(r[2]), "=r"(r[3]) : "r"(addr));
}
__device__ __forceinline__ void mma_bf16(float* c, const uint32_t* a, const uint32_t* b) {
    asm volatile("mma.sync.aligned.m16n8k16.row.col.f32.bf16.bf16.f32 "
        "{%0,%1,%2,%3}, {%4,%5,%6,%7}, {%8,%9}, {%0,%1,%2,%3};"
        : "+f"(c[0]), "+f"(c[1]), "+f"(c[2]), "+f"(c[3])
        : "r"(a[0]), "r"(a[1]), "r"(a[2]), "r"(a[3]), "r"(b[0]), "r"(b[1]));
}

// ------------------- init ----------------------------------------------------
__global__ void k_init0(const float* __restrict__ h0, const float* __restrict__ c0) {
    int i = blockIdx.x * blockDim.x + threadIdx.x;
    if (i < B * D) { g_h[i] = h0[i]; g_c[i] = c0[i]; }
    if (i < B * 2 * D) g_feed[i] = 0.f;
}

// ------------------- convert readout_W -> bf16 [hi|hi|lo] ---------------------
__global__ void k_convB(const float* __restrict__ RW) {
    int i = blockIdx.x * 256 + threadIdx.x;     // < V*D
    float v = RW[i];
    int r = i >> 10, d = i & 1023;
    __nv_bfloat16 hi = __float2bfloat16_rn(v);
    __nv_bfloat16 lo = __float2bfloat16_rn(v - __bfloat162float(hi));
    __nv_bfloat16* row = g_Bbf + (size_t)r * KP;
    row[d] = hi; row[1024 + d] = hi; row[2048 + d] = lo;
}

// ------------------- gates GEMM (unchanged, passing) ---------------------------
__global__ void __launch_bounds__(256) k_gates(
    const float* __restrict__ word_emb, const int* __restrict__ y_train,
    const float* __restrict__ W_ih, const float* __restrict__ W_hh, int t) {
    __shared__ __align__(16) float xs[32][34];
    __shared__ __align__(16) float ws[32][132];
    __shared__ int yidx[B];
    int tid = threadIdx.x;
    int s  = blockIdx.y;
    int j0 = blockIdx.x * 128;
    int cx = tid & 15, ty = tid >> 4;
    int lr = tid & 31, lkq = tid >> 5;
    int lc = tid & 127, lh = tid >> 7;
    if (tid < B) yidx[tid] = y_train[tid * TT + t];
    __syncthreads();

    unsigned long long acc[2][4] = {};
    for (int kt = 0; kt < 32; kt++) {
        {
            int kg = kt * 32 + lkq * 4;
            const float* px;
            if (s == 0)      px = word_emb + (size_t)yidx[lr] * D + kg;
            else if (s == 1) px = g_feed + lr * 2 * D + kg;
            else if (s == 2) px = g_feed + lr * 2 * D + 1024 + kg;
            else             px = g_h + lr * D + kg;
            float4 v = *(const float4*)px;
            xs[lkq*4+0][lr] = v.x; xs[lkq*4+1][lr] = v.y;
            xs[lkq*4+2][lr] = v.z; xs[lkq*4+3][lr] = v.w;
        }
        {
            int kg = kt * 32 + lh * 16;
            const float* pw = (s < 3)
                ? W_ih + (size_t)(j0 + lc) * (3 * D) + s * 1024 + kg
                : W_hh + (size_t)(j0 + lc) * D + kg;
#pragma unroll
            for (int m = 0; m < 4; m++) {
                float4 v = *(const float4*)(pw + m * 4);
                int k = lh * 16 + m * 4;
                ws[k+0][lc] = v.x; ws[k+1][lc] = v.y;
                ws[k+2][lc] = v.z; ws[k+3][lc] = v.w;
            }
        }
        __syncthreads();
#pragma unroll
        for (int kk = 0; kk < 32; kk++) {
            float2 a = *(const float2*)&xs[kk][2 * ty];
            unsigned long long ax = dup2(a.x), ay = dup2(a.y);
            const ulonglong2* wp = (const ulonglong2*)&ws[kk][8 * cx];
            ulonglong2 w01 = wp[0], w23 = wp[1];
            ffma2(acc[0][0], ax, w01.x); ffma2(acc[0][1], ax, w01.y);
            ffma2(acc[0][2], ax, w23.x); ffma2(acc[0][3], ax, w23.y);
            ffma2(acc[1][0], ay, w01.x); ffma2(acc[1][1], ay, w01.y);
            ffma2(acc[1][2], ay, w23.x); ffma2(acc[1][3], ay, w23.y);
        }
        __syncthreads();
    }
#pragma unroll
    for (int r = 0; r < 2; r++) {
        float* o = &g_gatesp[s][(2*ty + r) * (4*D) + j0 + 8*cx];
        ((ulonglong2*)o)[0] = make_ulonglong2(acc[r][0], acc[r][1]);
        ((ulonglong2*)o)[1] = make_ulonglong2(acc[r][2], acc[r][3]);
    }
}

// ------------------- LSTM cell -------------------------------------------------
__global__ void k_cell(const float* __restrict__ b_ih, const float* __restrict__ b_hh) {
    int i = blockIdx.x * blockDim.x + threadIdx.x;
    int b = i >> 10, d = i & 1023;
    float ig = b_ih[d]       + b_hh[d];
    float fg = b_ih[D+d]     + b_hh[D+d];
    float gg = b_ih[2*D+d]   + b_hh[2*D+d];
    float og = b_ih[3*D+d]   + b_hh[3*D+d];
#pragma unroll
    for (int s = 0; s < 4; s++) {
        const float* g = g_gatesp[s] + b * 4 * D;
        ig += g[d]; fg += g[D+d]; gg += g[2*D+d]; og += g[3*D+d];
    }
    float si = 1.f / (1.f + expf(-ig));
    float sf = 1.f / (1.f + expf(-fg));
    float so = 1.f / (1.f + expf(-og));
    float c = sf * g_c[i] + si * tanhf(gg);
    g_c[i] = c;
    g_h[i] = so * tanhf(c);
}

// ------------------- hproj GEMM -------------------------------------------------
__global__ void __launch_bounds__(256) k_hproj(const float* __restrict__ Wt) {
    __shared__ __align__(16) float xs[32][34];
    __shared__ __align__(16) float ws[32][132];
    int tid = threadIdx.x;
    int s  = blockIdx.y;
    int j0 = blockIdx.x * 128;
    int cx = tid & 15, ty = tid >> 4;
    int lr = tid & 31, lkq = tid >> 5;
    int lc = tid & 127, lh = tid >> 7;

    unsigned long long acc[2][4] = {};
    for (int kt = 0; kt < 2; kt++) {
        int kbase = s * 64 + kt * 32;
        {
            float4 v = *(const float4*)(g_h + lr * D + kbase + lkq * 4);
            xs[lkq*4+0][lr] = v.x; xs[lkq*4+1][lr] = v.y;
            xs[lkq*4+2][lr] = v.z; xs[lkq*4+3][lr] = v.w;
        }
        {
            const float* pw = Wt + (size_t)(j0 + lc) * D + kbase + lh * 16;
#pragma unroll
            for (int m = 0; m < 4; m++) {
                float4 v = *(const float4*)(pw + m * 4);
                int k = lh * 16 + m * 4;
                ws[k+0][lc] = v.x; ws[k+1][lc] = v.y;
                ws[k+2][lc] = v.z; ws[k+3][lc] = v.w;
            }
        }
        __syncthreads();
#pragma unroll
        for (int kk = 0; kk < 32; kk++) {
            float2 a = *(const float2*)&xs[kk][2 * ty];
            unsigned long long ax = dup2(a.x), ay = dup2(a.y);
            const ulonglong2* wp = (const ulonglong2*)&ws[kk][8 * cx];
            ulonglong2 w01 = wp[0], w23 = wp[1];
            ffma2(acc[0][0], ax, w01.x); ffma2(acc[0][1], ax, w01.y);
            ffma2(acc[0][2], ax, w23.x); ffma2(acc[0][3], ax, w23.y);
            ffma2(acc[1][0], ay, w01.x); ffma2(acc[1][1], ay, w01.y);
            ffma2(acc[1][2], ay, w23.x); ffma2(acc[1][3], ay, w23.y);
        }
        __syncthreads();
    }
#pragma unroll
    for (int r = 0; r < 2; r++) {
        float* o = &g_hprojp[s][(2*ty + r) * D + j0 + 8*cx];
        ((ulonglong2*)o)[0] = make_ulonglong2(acc[r][0], acc[r][1]);
        ((ulonglong2*)o)[1] = make_ulonglong2(acc[r][2], acc[r][3]);
    }
}

// ------------------- fused attention --------------------------------------------
__global__ void __launch_bounds__(512) k_attn(
    const float* __restrict__ x_enc, const float* __restrict__ x_enc_k,
    const unsigned char* __restrict__ x_mask,
    const float* __restrict__ w_att, const float* __restrict__ w_att_b,
    const float* __restrict__ w_trg_b) {
    __shared__ float hp[D];
    __shared__ float wl[LX];
    int b = blockIdx.x;
    int tid = threadIdx.x;
    int lane = tid & 31, wid = tid >> 5;

#pragma unroll
    for (int d = tid; d < D; d += 512) {
        float sum = w_trg_b[d];
#pragma unroll
        for (int s = 0; s < 16; s++) sum += g_hprojp[s][b * D + d];
        hp[d] = sum;
    }
    __syncthreads();

    for (int l = wid; l < LX; l += 16) {
        const float* xk = x_enc_k + (size_t)(b * LX + l) * D;
        float s = 0.f;
#pragma unroll 8
        for (int i = 0; i < 32; i++) {
            int d = lane + i * 32;
            s += fast_tanh(xk[d] + hp[d]) * w_att[d];
        }
#pragma unroll
        for (int off = 16; off; off >>= 1) s += __shfl_xor_sync(0xffffffffu, s, off);
        if (lane == 0) {
            float tot = s + w_att_b[0];
            if (x_mask[b * LX + l]) tot = -1e9f;
            wl[l] = tot;
        }
    }
    __syncthreads();

    if (tid == 0) {
        float mx = -1e30f;
        for (int l = 0; l < LX; l++) mx = fmaxf(mx, wl[l]);
        float z = 0.f;
        for (int l = 0; l < LX; l++) { float e = expf(wl[l] - mx); wl[l] = e; z += e; }
        float inv = 1.f / z;
        for (int l = 0; l < LX; l++) wl[l] *= inv;
    }
    __syncthreads();

    {
        int d2 = tid * 4;
        const float4* xe = (const float4*)(x_enc + (size_t)b * LX * 2 * D + d2);
        float4 acc = make_float4(0.f, 0.f, 0.f, 0.f);
#pragma unroll 8
        for (int l = 0; l < LX; l++) {
            float w = wl[l];
            float4 xv = xe[(size_t)l * (2 * D / 4)];
            acc.x += w * xv.x; acc.y += w * xv.y;
            acc.z += w * xv.z; acc.w += w * xv.w;
        }
        *(float4*)&g_feed[b * 2 * D + d2] = acc;
    }
}

// ------------------- pre GEMM -----------------------------------------------------
__global__ void __launch_bounds__(256) k_pre(const float* __restrict__ Cw) {
    __shared__ __align__(16) float xs[32][34];
    __shared__ __align__(16) float ws[32][132];
    int tid = threadIdx.x;
    int s  = blockIdx.y;
    int j0 = blockIdx.x * 128;
    int cx = tid & 15, ty = tid >> 4;
    int lr = tid & 31, lkq = tid >> 5;
    int lc = tid & 127, lh = tid >> 7;

    unsigned long long acc[2][4] = {};
    for (int kt = 0; kt < 6; kt++) {
        int kbase = s * 192 + kt * 32;
        {
            int k = kbase + lkq * 4;
            const float* px = (k < D) ? (g_h + lr * D + k)
                                      : (g_feed + lr * 2 * D + (k - D));
            float4 v = *(const float4*)px;
            xs[lkq*4+0][lr] = v.x; xs[lkq*4+1][lr] = v.y;
            xs[lkq*4+2][lr] = v.z; xs[lkq*4+3][lr] = v.w;
        }
        {
            const float* pw = Cw + (size_t)(j0 + lc) * (3 * D) + kbase + lh * 16;
#pragma unroll
            for (int m = 0; m < 4; m++) {
                float4 v = *(const float4*)(pw + m * 4);
                int k = lh * 16 + m * 4;
                ws[k+0][lc] = v.x; ws[k+1][lc] = v.y;
                ws[k+2][lc] = v.z; ws[k+3][lc] = v.w;
            }
        }
        __syncthreads();
#pragma unroll
        for (int kk = 0; kk < 32; kk++) {
            float2 a = *(const float2*)&xs[kk][2 * ty];
            unsigned long long ax = dup2(a.x), ay = dup2(a.y);
            const ulonglong2* wp = (const ulonglong2*)&ws[kk][8 * cx];
            ulonglong2 w01 = wp[0], w23 = wp[1];
            ffma2(acc[0][0], ax, w01.x); ffma2(acc[0][1], ax, w01.y);
            ffma2(acc[0][2], ax, w23.x); ffma2(acc[0][3], ax, w23.y);
            ffma2(acc[1][0], ay, w01.x); ffma2(acc[1][1], ay, w01.y);
            ffma2(acc[1][2], ay, w23.x); ffma2(acc[1][3], ay, w23.y);
        }
        __syncthreads();
    }
#pragma unroll
    for (int r = 0; r < 2; r++) {
        float* o = &g_prep[s][(2*ty + r) * D + j0 + 8*cx];
        ((ulonglong2*)o)[0] = make_ulonglong2(acc[r][0], acc[r][1]);
        ((ulonglong2*)o)[1] = make_ulonglong2(acc[r][2], acc[r][3]);
    }
}

// ------------------- pretanh -> write A' bf16 hi/lo rows --------------------------
__global__ void k_pretanh(int t) {
    int i = blockIdx.x * blockDim.x + threadIdx.x;     // < B*D
    float v = 0.f;
#pragma unroll
    for (int s = 0; s < 16; s++) v += g_prep[s][i];
    v = tanhf(v);
    int b = i >> 10, d = i & 1023;
    int m = t * B + b;
    __nv_bfloat16 hi = __float2bfloat16_rn(v);
    __nv_bfloat16 lo = __float2bfloat16_rn(v - __bfloat162float(hi));
    __nv_bfloat16* row = g_Abf + (size_t)m * KP;
    row[d] = hi; row[1024 + d] = lo; row[2048 + d] = hi;
}

// ------------------- logits GEMM via mma.sync (base-ISA tensor cores) -------------
// C[2048,32000] = A'[2048,3072] @ B'[32000,3072]^T, fp32 accum.
// CTA 128x128, 8 warps (2M x 4N), warp 64x32, K-chunk 32, 2-stage cp.async.
__global__ void __launch_bounds__(256, 2) k_logits_mma(float* __restrict__ out) {
    __shared__ __align__(16) __nv_bfloat16 sA[2][128][40];   // 80B rows (16B pad)
    __shared__ __align__(16) __nv_bfloat16 sB[2][128][40];
    int tid = threadIdx.x;
    int lane = tid & 31, wid = tid >> 5;
    int warpM = wid & 1, warpN = wid >> 1;
    int row0 = blockIdx.x * 128;       // M tiles (16)
    int col0 = blockIdx.y * 128;       // N tiles (250)

    // lane-dependent ldmatrix offsets
    int a_row = (lane & 7) + ((lane >> 3) & 1) * 8;
    int a_k   = (lane >> 4) * 8;
    int b_row = (lane & 7) + (lane >> 4) * 8;
    int b_k   = ((lane >> 3) & 1) * 8;
    uint32_t aBase = smem_u32(&sA[0][0][0]) + (warpM * 64 + a_row) * 80 + a_k * 2;
    uint32_t bBase = smem_u32(&sB[0][0][0]) + (warpN * 32 + b_row) * 80 + b_k * 2;

    // cp.async assignment: 512 16B-chunks per matrix per stage, 2 per thread
    int ldr = tid >> 2;                // row 0..63 (+128 on q=1)
    int ldi = tid & 3;                 // 16B chunk in row

    float acc[4][4][4];
#pragma unroll
    for (int i = 0; i < 4; i++)
#pragma unroll
        for (int j = 0; j < 4; j++)
#pragma unroll
            for (int q = 0; q < 4; q++) acc[i][j][q] = 0.f;

    // prologue: stage 0 of chunk 0
#pragma unroll
    for (int q = 0; q < 2; q++) {
        int r = ldr + q * 64;
        cpasync16(smem_u32(&sA[0][r][ldi * 8]), g_Abf + (size_t)(row0 + r) * KP + ldi * 8);
        cpasync16(smem_u32(&sB[0][r][ldi * 8]), g_Bbf + (size_t)(col0 + r) * KP + ldi * 8);
    }
    asm volatile("cp.async.commit_group;" ::: "memory");

    const int NCH = KP / 32;           // 96
    for (int i = 0; i < NCH; i++) {
        int st = i & 1;
        if (i + 1 < NCH) {
            int ns = st ^ 1;
            int kb = (i + 1) * 32;
#pragma unroll
            for (int q = 0; q < 2; q++) {
                int r = ldr + q * 64;
                cpasync16(smem_u32(&sA[ns][r][ldi * 8]),
                          g_Abf + (size_t)(row0 + r) * KP + kb + ldi * 8);
                cpasync16(smem_u32(&sB[ns][r][ldi * 8]),
                          g_Bbf + (size_t)(col0 + r) * KP + kb + ldi * 8);
            }
            asm volatile("cp.async.commit_group;" ::: "memory");
            asm volatile("cp.async.wait_group 1;" ::: "memory");
        } else {
            asm volatile("cp.async.wait_group 0;" ::: "memory");
        }
        __syncthreads();

        uint32_t stoff = st * (uint32_t)(128 * 80);
#pragma unroll
        for (int k16 = 0; k16 < 2; k16++) {
            uint32_t koff = stoff + k16 * 32;
            uint32_t a[4][4], b[2][4];
#pragma unroll
            for (int mt = 0; mt < 4; mt++) ldm_x4(a[mt], aBase + koff + mt * 1280);
#pragma unroll
            for (int p = 0; p < 2; p++)    ldm_x4(b[p], bBase + koff + p * 1280);
#pragma unroll
            for (int mt = 0; mt < 4; mt++)
#pragma unroll
                for (int nt = 0; nt < 4; nt++)
                    mma_bf16(acc[mt][nt], a[mt], &b[nt >> 1][(nt & 1) * 2]);
        }
        __syncthreads();
    }

    // epilogue
    int grp = lane >> 2, tig = lane & 3;
#pragma unroll
    for (int mt = 0; mt < 4; mt++) {
        int m1 = row0 + warpM * 64 + mt * 16 + grp;
        int m2 = m1 + 8;
        float* o1 = out + ((size_t)(m1 & 31) * TT + (m1 >> 5)) * V;
        float* o2 = out + ((size_t)(m2 & 31) * TT + (m2 >> 5)) * V;
#pragma unroll
        for (int nt = 0; nt < 4; nt++) {
            int n = col0 + warpN * 32 + nt * 8 + tig * 2;
            *(float2*)(o1 + n) = make_float2(acc[mt][nt][0], acc[mt][nt][1]);
            *(float2*)(o2 + n) = make_float2(acc[mt][nt][2], acc[mt][nt][3]);
        }
    }
}

// ------------------- launch ---------------------------------------------------------
extern "C" void kernel_launch(void* const* d_in, const int* in_sizes, int n_in,
                              void* d_out, int out_size) {
    const float* x_enc      = (const float*)d_in[0];
    const float* x_enc_k    = (const float*)d_in[1];
    const float* h0         = (const float*)d_in[2];
    const float* c0         = (const float*)d_in[3];
    const unsigned char* xm = (const unsigned char*)d_in[4];
    const int*   y_train    = (const int*)d_in[5];
    const float* word_emb   = (const float*)d_in[6];
    const float* W_ih       = (const float*)d_in[7];
    const float* W_hh       = (const float*)d_in[8];
    const float* b_ih       = (const float*)d_in[9];
    const float* b_hh       = (const float*)d_in[10];
    const float* w_trg_W    = (const float*)d_in[11];
    const float* w_trg_b    = (const float*)d_in[12];
    const float* w_att      = (const float*)d_in[13];
    const float* w_att_b    = (const float*)d_in[14];
    const float* ctx_W      = (const float*)d_in[15];
    const float* RW         = (const float*)d_in[16];
    float* out = (float*)d_out;

    k_convB<<<(V * D) / 256, 256>>>(RW);
    k_init0<<<(B * 2 * D + 255) / 256, 256>>>(h0, c0);
    for (int t = 0; t < TT; t++) {
        k_gates<<<dim3(32, 4), 256>>>(word_emb, y_train, W_ih, W_hh, t);
        k_cell<<<B * D / 256, 256>>>(b_ih, b_hh);
        k_hproj<<<dim3(8, 16), 256>>>(w_trg_W);
        k_attn<<<B, 512>>>(x_enc, x_enc_k, xm, w_att, w_att_b, w_trg_b);
        k_pre<<<dim3(8, 16), 256>>>(ctx_W);
        k_pretanh<<<B * D / 256, 256>>>(t);
    }
    k_logits_mma<<<dim3((B * TT) / 128, V / 128), 256>>>(out);
}

// round 5
// speedup vs baseline: 1.8834x; 1.6262x over previous
#include <cuda_runtime.h>
#include <cuda_bf16.h>
#include <math.h>
#include <stdint.h>

#define B  32
#define LX 64
#define TT 64
#define D  1024
#define V  32000
#define KP 3072
#define GRIDN 128

// ------------------- device globals (no allocation) ---------------------------
__device__ float g_h[B * D];
__device__ float g_c[B * D];
__device__ float g_feed[B * 2 * D];
__device__ float g_gatesp2[4 * 64 * 4096];     // gates partials [split][64][4096]
__device__ float g_hprojp2[16 * 64 * 1024];    // hproj partials
__device__ float g_prep2[16 * 64 * 1024];      // pre partials
__device__ __align__(16) __nv_bfloat16 g_Abf[(TT * B) * KP];       // logits A'
__device__ __align__(16) __nv_bfloat16 g_Bbf[(size_t)V * KP];      // logits B'
__device__ __align__(16) __nv_bfloat16 g_Wg2[(size_t)4096 * 8192]; // gates W2
__device__ __align__(16) __nv_bfloat16 g_Wh2[1024 * 2048];         // hproj W2
__device__ __align__(16) __nv_bfloat16 g_Wp2[1024 * 6144];         // pre W2
__device__ unsigned g_arrive;
__device__ volatile unsigned g_release;

// ------------------- helpers ---------------------------------------------------
__device__ __forceinline__ float fast_tanh(float x) {
    float e = __expf(2.f * x);
    return 1.f - __fdividef(2.f, e + 1.f);
}
__device__ __forceinline__ uint32_t smem_u32(const void* p) {
    uint32_t a;
    asm("{ .reg .u64 t; cvta.to.shared.u64 t, %1; cvt.u32.u64 %0, t; }" : "=r"(a) : "l"(p));
    return a;
}
__device__ __forceinline__ void cpasync16(uint32_t dst, const void* src) {
    asm volatile("cp.async.cg.shared.global [%0], [%1], 16;" :: "r"(dst), "l"(src));
}
__device__ __forceinline__ void ldm_x4(uint32_t* r, uint32_t addr) {
    asm volatile("ldmatrix.sync.aligned.m8n8.x4.shared.b16 {%0,%1,%2,%3}, [%4];"
        : "=r"(r[0]), "=r"(r[1]), "=r"(r[2]), "=r"(r[3]) : "r"(addr));
}
__device__ __forceinline__ void mma_bf16(float* c, const uint32_t* a, const uint32_t* b) {
    asm volatile("mma.sync.aligned.m16n8k16.row.col.f32.bf16.bf16.f32 "
        "{%0,%1,%2,%3}, {%4,%5,%6,%7}, {%8,%9}, {%0,%1,%2,%3};"
        : "+f"(c[0]), "+f"(c[1]), "+f"(c[2]), "+f"(c[3])
        : "r"(a[0]), "r"(a[1]), "r"(a[2]), "r"(a[3]), "r"(b[0]), "r"(b[1]));
}

// ------------------- grid barrier (persistent kernel) ---------------------------
__device__ __forceinline__ void gridbar(unsigned gen) {
    __threadfence();
    __syncthreads();
    if (threadIdx.x == 0) {
        unsigned a = atomicAdd(&g_arrive, 1u) + 1u;
        if (a == gen * GRIDN) {
            atomicExch((unsigned*)&g_release, gen);
        } else {
            while (g_release < gen) __nanosleep(64);
        }
    }
    __syncthreads();
}

// ------------------- init + weight conversions ----------------------------------
__global__ void k_init0(const float* __restrict__ h0, const float* __restrict__ c0) {
    int i = blockIdx.x * blockDim.x + threadIdx.x;
    if (i == 0) { g_arrive = 0; g_release = 0; }
    if (i < B * D) { g_h[i] = h0[i]; g_c[i] = c0[i]; }
    if (i < B * 2 * D) g_feed[i] = 0.f;
}

__global__ void k_convB(const float* __restrict__ RW) {
    int i = blockIdx.x * 256 + threadIdx.x;     // < V*D
    float v = RW[i];
    int r = i >> 10, d = i & 1023;
    __nv_bfloat16 hi = __float2bfloat16_rn(v);
    __nv_bfloat16 lo = __float2bfloat16_rn(v - __bfloat162float(hi));
    __nv_bfloat16* row = g_Bbf + (size_t)r * KP;
    row[d] = hi; row[1024 + d] = hi; row[2048 + d] = lo;
}

__global__ void k_convWg(const float* __restrict__ Wih, const float* __restrict__ Whh) {
    int k = blockIdx.x * 256 + threadIdx.x;     // 0..4095
    int j = blockIdx.y;                          // 0..4095
    float v = (k < 3072) ? Wih[(size_t)j * 3072 + k] : Whh[(size_t)j * 1024 + (k - 3072)];
    __nv_bfloat16 hi = __float2bfloat16_rn(v);
    __nv_bfloat16 lo = __float2bfloat16_rn(v - __bfloat162float(hi));
    g_Wg2[(size_t)j * 8192 + k] = hi;
    g_Wg2[(size_t)j * 8192 + 4096 + k] = lo;
}
__global__ void k_convWh(const float* __restrict__ Wt) {
    int k = blockIdx.x * 256 + threadIdx.x;     // 0..1023
    int j = blockIdx.y;                          // 0..1023
    float v = Wt[(size_t)j * 1024 + k];
    __nv_bfloat16 hi = __float2bfloat16_rn(v);
    __nv_bfloat16 lo = __float2bfloat16_rn(v - __bfloat162float(hi));
    g_Wh2[j * 2048 + k] = hi;
    g_Wh2[j * 2048 + 1024 + k] = lo;
}
__global__ void k_convWp(const float* __restrict__ Cw) {
    int k = blockIdx.x * 256 + threadIdx.x;     // 0..3071
    int j = blockIdx.y;                          // 0..1023
    float v = Cw[(size_t)j * 3072 + k];
    __nv_bfloat16 hi = __float2bfloat16_rn(v);
    __nv_bfloat16 lo = __float2bfloat16_rn(v - __bfloat162float(hi));
    g_Wp2[j * 6144 + k] = hi;
    g_Wp2[j * 6144 + 3072 + k] = lo;
}

// ------------------- persistent step kernel --------------------------------------
struct MmaSmem {
    __nv_bfloat16 A[2][64][40];      // 10240 B
    __nv_bfloat16 Bt[2][128][40];    // 20480 B
};

__device__ __forceinline__ float4 fetch_src(int mode, int rsrc, int kglob, int khalf,
    const float* __restrict__ word_emb, const int* __restrict__ y_train, int t) {
    int ksrc = (kglob < khalf) ? kglob : kglob - khalf;
    if (mode == 0) {
        if (ksrc < 1024) {
            int y = y_train[rsrc * TT + t];
            return *(const float4*)(word_emb + (size_t)y * D + ksrc);
        } else if (ksrc < 3072) {
            return __ldcg((const float4*)&g_feed[rsrc * 2048 + (ksrc - 1024)]);
        }
        return __ldcg((const float4*)&g_h[rsrc * 1024 + (ksrc - 3072)]);
    } else if (mode == 1) {
        return __ldcg((const float4*)&g_h[rsrc * 1024 + ksrc]);
    }
    if (ksrc < 1024) return __ldcg((const float4*)&g_h[rsrc * 1024 + ksrc]);
    return __ldcg((const float4*)&g_feed[rsrc * 2048 + (ksrc - 1024)]);
}

__device__ __forceinline__ void storeA(MmaSmem* sm, int st, int r, int k4,
                                       float4 v, bool dolo) {
    __nv_bfloat16 h0 = __float2bfloat16_rn(v.x), h1 = __float2bfloat16_rn(v.y);
    __nv_bfloat16 h2 = __float2bfloat16_rn(v.z), h3 = __float2bfloat16_rn(v.w);
    __nv_bfloat162* ph = (__nv_bfloat162*)&sm->A[st][r][k4];
    __nv_bfloat162 t0; t0.x = h0; t0.y = h1; ph[0] = t0;
    __nv_bfloat162 t1; t1.x = h2; t1.y = h3; ph[1] = t1;
    __nv_bfloat162* pl = (__nv_bfloat162*)&sm->A[st][r + 32][k4];
    if (dolo) {
        __nv_bfloat162 l0, l1;
        l0.x = __float2bfloat16_rn(v.x - __bfloat162float(h0));
        l0.y = __float2bfloat16_rn(v.y - __bfloat162float(h1));
        l1.x = __float2bfloat16_rn(v.z - __bfloat162float(h2));
        l1.y = __float2bfloat16_rn(v.w - __bfloat162float(h3));
        pl[0] = l0; pl[1] = l1;
    } else {
        __nv_bfloat162 z; z.x = __float2bfloat16_rn(0.f); z.y = z.x;
        pl[0] = z; pl[1] = z;
    }
}

// M=64 x 128-col tile MMA phase: C = A2 @ B2^T partial over K-split.
__device__ void mma_phase(MmaSmem* sm, const __nv_bfloat16* __restrict__ B2,
                          float* __restrict__ part,
                          int ncols, int K2, int khalf, int nch, int col0, int split,
                          int mode, const float* __restrict__ word_emb,
                          const int* __restrict__ y_train, int t) {
    int tid = threadIdx.x;
    int lane = tid & 31, wid = tid >> 5;
    int warpM = wid & 1, warpN = wid >> 1;
    int kbase0 = split * (nch * 32);

    int a_row = (lane & 7) + ((lane >> 3) & 1) * 8;
    int a_k   = (lane >> 4) * 8;
    int b_row = (lane & 7) + (lane >> 4) * 8;
    int b_k   = ((lane >> 3) & 1) * 8;
    uint32_t aB = smem_u32(&sm->A[0][0][0])  + ((warpM * 32 + a_row) * 40 + a_k) * 2;
    uint32_t bB = smem_u32(&sm->Bt[0][0][0]) + ((warpN * 32 + b_row) * 40 + b_k) * 2;

    int rsrc = tid >> 3;
    int kk4  = (tid & 7) * 4;

    float acc[2][4][4];
#pragma unroll
    for (int a = 0; a < 2; a++)
#pragma unroll
        for (int b = 0; b < 4; b++)
#pragma unroll
            for (int q = 0; q < 4; q++) acc[a][b][q] = 0.f;

    // prologue: A(0) fill + B(0) cp.async
    {
        float4 v = fetch_src(mode, rsrc, kbase0 + kk4, khalf, word_emb, y_train, t);
        storeA(sm, 0, rsrc, kk4, v, (kbase0 + kk4) < khalf);
#pragma unroll
        for (int q = 0; q < 2; q++) {
            int a2 = q * 256 + tid;
            int r = a2 >> 2, li = a2 & 3;
            cpasync16(smem_u32(&sm->Bt[0][r][li * 8]),
                      B2 + (size_t)(col0 + r) * K2 + kbase0 + li * 8);
        }
        asm volatile("cp.async.commit_group;" ::: "memory");
    }

    for (int i = 0; i < nch; i++) {
        int st = i & 1;
        bool more = (i + 1 < nch);
        float4 vnext;
        if (more) {
            int kb1 = kbase0 + (i + 1) * 32;
#pragma unroll
            for (int q = 0; q < 2; q++) {
                int a2 = q * 256 + tid;
                int r = a2 >> 2, li = a2 & 3;
                cpasync16(smem_u32(&sm->Bt[st ^ 1][r][li * 8]),
                          B2 + (size_t)(col0 + r) * K2 + kb1 + li * 8);
            }
            asm volatile("cp.async.commit_group;" ::: "memory");
            vnext = fetch_src(mode, rsrc, kb1 + kk4, khalf, word_emb, y_train, t);
            asm volatile("cp.async.wait_group 1;" ::: "memory");
        } else {
            asm volatile("cp.async.wait_group 0;" ::: "memory");
        }
        __syncthreads();

#pragma unroll
        for (int k16 = 0; k16 < 2; k16++) {
            uint32_t ao = st * 5120u  + k16 * 32u;
            uint32_t bo = st * 10240u + k16 * 32u;
            uint32_t a0[4], a1[4], bb[2][4];
            ldm_x4(a0, aB + ao);
            ldm_x4(a1, aB + ao + 1280);
            ldm_x4(bb[0], bB + bo);
            ldm_x4(bb[1], bB + bo + 1280);
#pragma unroll
            for (int nt = 0; nt < 4; nt++) {
                mma_bf16(acc[0][nt], a0, &bb[nt >> 1][(nt & 1) * 2]);
                mma_bf16(acc[1][nt], a1, &bb[nt >> 1][(nt & 1) * 2]);
            }
        }
        if (more) {
            int kb1 = kbase0 + (i + 1) * 32;
            storeA(sm, st ^ 1, rsrc, kk4, vnext, (kb1 + kk4) < khalf);
        }
        __syncthreads();
    }

    // epilogue → partials
    int grp = lane >> 2, tig = lane & 3;
#pragma unroll
    for (int mt = 0; mt < 2; mt++) {
        int m1 = warpM * 32 + mt * 16 + grp;
        int m2 = m1 + 8;
        float* p1 = part + (size_t)(split * 64 + m1) * ncols + col0 + warpN * 32;
        float* p2 = part + (size_t)(split * 64 + m2) * ncols + col0 + warpN * 32;
#pragma unroll
        for (int nt = 0; nt < 4; nt++) {
            int n = nt * 8 + tig * 2;
            *(float2*)(p1 + n) = make_float2(acc[mt][nt][0], acc[mt][nt][1]);
            *(float2*)(p2 + n) = make_float2(acc[mt][nt][2], acc[mt][nt][3]);
        }
    }
}

__device__ void cell_work(int bid, const float* __restrict__ b_ih,
                          const float* __restrict__ b_hh) {
    int id = bid * 256 + threadIdx.x;           // 0..32767
    int m = id >> 10, d = id & 1023;
    float ig = b_ih[d]        + b_hh[d];
    float fg = b_ih[1024 + d] + b_hh[1024 + d];
    float gg = b_ih[2048 + d] + b_hh[2048 + d];
    float og = b_ih[3072 + d] + b_hh[3072 + d];
#pragma unroll
    for (int s = 0; s < 4; s++) {
        const float* p0 = g_gatesp2 + (size_t)(s * 64 + m) * 4096;
        const float* p1 = g_gatesp2 + (size_t)(s * 64 + 32 + m) * 4096;
        ig += __ldcg(p0 + d)        + __ldcg(p1 + d);
        fg += __ldcg(p0 + 1024 + d) + __ldcg(p1 + 1024 + d);
        gg += __ldcg(p0 + 2048 + d) + __ldcg(p1 + 2048 + d);
        og += __ldcg(p0 + 3072 + d) + __ldcg(p1 + 3072 + d);
    }
    float si = 1.f / (1.f + expf(-ig));
    float sf = 1.f / (1.f + expf(-fg));
    float so = 1.f / (1.f + expf(-og));
    float c = sf * __ldcg(&g_c[id]) + si * tanhf(gg);
    g_c[id] = c;
    g_h[id] = so * tanhf(c);
}

__device__ void pretanh_work(int t, int bid) {
    int id = bid * 256 + threadIdx.x;           // 0..32767
    int m = id >> 10, d = id & 1023;
    float v = 0.f;
#pragma unroll
    for (int s = 0; s < 16; s++) {
        v += __ldcg(&g_prep2[(size_t)(s * 64 + m) * 1024 + d]);
        v += __ldcg(&g_prep2[(size_t)(s * 64 + 32 + m) * 1024 + d]);
    }
    v = tanhf(v);
    int row = t * B + m;
    __nv_bfloat16 hi = __float2bfloat16_rn(v);
    __nv_bfloat16 lo = __float2bfloat16_rn(v - __bfloat162float(hi));
    __nv_bfloat16* arow = g_Abf + (size_t)row * KP;
    arow[d] = hi; arow[1024 + d] = lo; arow[2048 + d] = hi;
}

__device__ void attn_work(int b, float* s_hp, float* s_wl,
                          const float* __restrict__ x_enc,
                          const float* __restrict__ x_enc_k,
                          const unsigned char* __restrict__ xm,
                          const float* __restrict__ w_trg_b,
                          const float* __restrict__ w_att,
                          const float* __restrict__ w_att_b) {
    int tid = threadIdx.x;
    int lane = tid & 31, wd = tid >> 5;
    for (int d = tid; d < 1024; d += 256) {
        float sum = w_trg_b[d];
#pragma unroll
        for (int s = 0; s < 16; s++) {
            sum += __ldcg(&g_hprojp2[(size_t)(s * 64 + b) * 1024 + d]);
            sum += __ldcg(&g_hprojp2[(size_t)(s * 64 + 32 + b) * 1024 + d]);
        }
        s_hp[d] = sum;
    }
    __syncthreads();
    for (int l = wd; l < LX; l += 8) {
        const float* xk = x_enc_k + ((size_t)b * LX + l) * D;
        float s = 0.f;
#pragma unroll 8
        for (int i = 0; i < 32; i++) {
            int d = lane + i * 32;
            s += fast_tanh(xk[d] + s_hp[d]) * w_att[d];
        }
#pragma unroll
        for (int off = 16; off; off >>= 1) s += __shfl_xor_sync(0xffffffffu, s, off);
        if (lane == 0) {
            float tot = s + w_att_b[0];
            if (xm[b * LX + l]) tot = -1e9f;
            s_wl[l] = tot;
        }
    }
    __syncthreads();
    if (tid == 0) {
        float mx = -1e30f;
        for (int l = 0; l < LX; l++) mx = fmaxf(mx, s_wl[l]);
        float z = 0.f;
        for (int l = 0; l < LX; l++) { float e = expf(s_wl[l] - mx); s_wl[l] = e; z += e; }
        float inv = 1.f / z;
        for (int l = 0; l < LX; l++) s_wl[l] *= inv;
    }
    __syncthreads();
    {
        int d2 = tid * 8;
        const float* xe = x_enc + (size_t)b * LX * 2048 + d2;
        float4 a0 = make_float4(0.f, 0.f, 0.f, 0.f);
        float4 a1 = make_float4(0.f, 0.f, 0.f, 0.f);
#pragma unroll 8
        for (int l = 0; l < LX; l++) {
            float w = s_wl[l];
            float4 x0 = *(const float4*)(xe + (size_t)l * 2048);
            float4 x1 = *(const float4*)(xe + (size_t)l * 2048 + 4);
            a0.x += w * x0.x; a0.y += w * x0.y; a0.z += w * x0.z; a0.w += w * x0.w;
            a1.x += w * x1.x; a1.y += w * x1.y; a1.z += w * x1.z; a1.w += w * x1.w;
        }
        *(float4*)&g_feed[b * 2048 + d2]     = a0;
        *(float4*)&g_feed[b * 2048 + d2 + 4] = a1;
    }
}

__global__ void __launch_bounds__(256, 1) k_steps(
    const float* __restrict__ x_enc, const float* __restrict__ x_enc_k,
    const unsigned char* __restrict__ xm, const int* __restrict__ y_train,
    const float* __restrict__ word_emb,
    const float* __restrict__ b_ih, const float* __restrict__ b_hh,
    const float* __restrict__ w_trg_b, const float* __restrict__ w_att,
    const float* __restrict__ w_att_b) {
    __shared__ MmaSmem sm;
    __shared__ float s_hp[1024];
    __shared__ float s_wl[LX];
    int bid = blockIdx.x;
    unsigned gen = 0;

    for (int t = 0; t < TT; t++) {
        // phase 1: pretanh(t-1) + gates MMA
        if (t > 0) pretanh_work(t - 1, bid);
        mma_phase(&sm, g_Wg2, g_gatesp2, 4096, 8192, 4096, 64,
                  (bid & 31) * 128, bid >> 5, 0, word_emb, y_train, t);
        gridbar(++gen);
        // phase 2: LSTM cell
        cell_work(bid, b_ih, b_hh);
        gridbar(++gen);
        // phase 3: hproj MMA
        mma_phase(&sm, g_Wh2, g_hprojp2, 1024, 2048, 1024, 4,
                  (bid & 7) * 128, bid >> 3, 1, word_emb, y_train, t);
        gridbar(++gen);
        // phase 4: attention (32 CTAs)
        if (bid < 32)
            attn_work(bid, s_hp, s_wl, x_enc, x_enc_k, xm, w_trg_b, w_att, w_att_b);
        gridbar(++gen);
        // phase 5: pre MMA
        mma_phase(&sm, g_Wp2, g_prep2, 1024, 6144, 3072, 12,
                  (bid & 7) * 128, bid >> 3, 2, word_emb, y_train, t);
        gridbar(++gen);
    }
    pretanh_work(TT - 1, bid);
}

// ------------------- logits GEMM via mma.sync (unchanged, passing) ----------------
__global__ void __launch_bounds__(256, 2) k_logits_mma(float* __restrict__ out) {
    __shared__ __align__(16) __nv_bfloat16 sA[2][128][40];
    __shared__ __align__(16) __nv_bfloat16 sB[2][128][40];
    int tid = threadIdx.x;
    int lane = tid & 31, wid = tid >> 5;
    int warpM = wid & 1, warpN = wid >> 1;
    int row0 = blockIdx.x * 128;
    int col0 = blockIdx.y * 128;

    int a_row = (lane & 7) + ((lane >> 3) & 1) * 8;
    int a_k   = (lane >> 4) * 8;
    int b_row = (lane & 7) + (lane >> 4) * 8;
    int b_k   = ((lane >> 3) & 1) * 8;
    uint32_t aBase = smem_u32(&sA[0][0][0]) + (warpM * 64 + a_row) * 80 + a_k * 2;
    uint32_t bBase = smem_u32(&sB[0][0][0]) + (warpN * 32 + b_row) * 80 + b_k * 2;

    int ldr = tid >> 2;
    int ldi = tid & 3;

    float acc[4][4][4];
#pragma unroll
    for (int i = 0; i < 4; i++)
#pragma unroll
        for (int j = 0; j < 4; j++)
#pragma unroll
            for (int q = 0; q < 4; q++) acc[i][j][q] = 0.f;

#pragma unroll
    for (int q = 0; q < 2; q++) {
        int r = ldr + q * 64;
        cpasync16(smem_u32(&sA[0][r][ldi * 8]), g_Abf + (size_t)(row0 + r) * KP + ldi * 8);
        cpasync16(smem_u32(&sB[0][r][ldi * 8]), g_Bbf + (size_t)(col0 + r) * KP + ldi * 8);
    }
    asm volatile("cp.async.commit_group;" ::: "memory");

    const int NCH = KP / 32;
    for (int i = 0; i < NCH; i++) {
        int st = i & 1;
        if (i + 1 < NCH) {
            int ns = st ^ 1;
            int kb = (i + 1) * 32;
#pragma unroll
            for (int q = 0; q < 2; q++) {
                int r = ldr + q * 64;
                cpasync16(smem_u32(&sA[ns][r][ldi * 8]),
                          g_Abf + (size_t)(row0 + r) * KP + kb + ldi * 8);
                cpasync16(smem_u32(&sB[ns][r][ldi * 8]),
                          g_Bbf + (size_t)(col0 + r) * KP + kb + ldi * 8);
            }
            asm volatile("cp.async.commit_group;" ::: "memory");
            asm volatile("cp.async.wait_group 1;" ::: "memory");
        } else {
            asm volatile("cp.async.wait_group 0;" ::: "memory");
        }
        __syncthreads();

        uint32_t stoff = st * (uint32_t)(128 * 80);
#pragma unroll
        for (int k16 = 0; k16 < 2; k16++) {
            uint32_t koff = stoff + k16 * 32;
            uint32_t a[4][4], b[2][4];
#pragma unroll
            for (int mt = 0; mt < 4; mt++) ldm_x4(a[mt], aBase + koff + mt * 1280);
#pragma unroll
            for (int p = 0; p < 2; p++)    ldm_x4(b[p], bBase + koff + p * 1280);
#pragma unroll
            for (int mt = 0; mt < 4; mt++)
#pragma unroll
                for (int nt = 0; nt < 4; nt++)
                    mma_bf16(acc[mt][nt], a[mt], &b[nt >> 1][(nt & 1) * 2]);
        }
        __syncthreads();
    }

    int grp = lane >> 2, tig = lane & 3;
#pragma unroll
    for (int mt = 0; mt < 4; mt++) {
        int m1 = row0 + warpM * 64 + mt * 16 + grp;
        int m2 = m1 + 8;
        float* o1 = out + ((size_t)(m1 & 31) * TT + (m1 >> 5)) * V;
        float* o2 = out + ((size_t)(m2 & 31) * TT + (m2 >> 5)) * V;
#pragma unroll
        for (int nt = 0; nt < 4; nt++) {
            int n = col0 + warpN * 32 + nt * 8 + tig * 2;
            *(float2*)(o1 + n) = make_float2(acc[mt][nt][0], acc[mt][nt][1]);
            *(float2*)(o2 + n) = make_float2(acc[mt][nt][2], acc[mt][nt][3]);
        }
    }
}

// ------------------- launch ---------------------------------------------------------
extern "C" void kernel_launch(void* const* d_in, const int* in_sizes, int n_in,
                              void* d_out, int out_size) {
    const float* x_enc      = (const float*)d_in[0];
    const float* x_enc_k    = (const float*)d_in[1];
    const float* h0         = (const float*)d_in[2];
    const float* c0         = (const float*)d_in[3];
    const unsigned char* xm = (const unsigned char*)d_in[4];
    const int*   y_train    = (const int*)d_in[5];
    const float* word_emb   = (const float*)d_in[6];
    const float* W_ih       = (const float*)d_in[7];
    const float* W_hh       = (const float*)d_in[8];
    const float* b_ih       = (const float*)d_in[9];
    const float* b_hh       = (const float*)d_in[10];
    const float* w_trg_W    = (const float*)d_in[11];
    const float* w_trg_b    = (const float*)d_in[12];
    const float* w_att      = (const float*)d_in[13];
    const float* w_att_b    = (const float*)d_in[14];
    const float* ctx_W      = (const float*)d_in[15];
    const float* RW         = (const float*)d_in[16];
    float* out = (float*)d_out;

    k_convB<<<(V * D) / 256, 256>>>(RW);
    k_convWg<<<dim3(16, 4096), 256>>>(W_ih, W_hh);
    k_convWh<<<dim3(4, 1024), 256>>>(w_trg_W);
    k_convWp<<<dim3(12, 1024), 256>>>(ctx_W);
    k_init0<<<(B * 2 * D + 255) / 256, 256>>>(h0, c0);
    k_steps<<<GRIDN, 256>>>(x_enc, x_enc_k, xm, y_train, word_emb,
                            b_ih, b_hh, w_trg_b, w_att, w_att_b);
    k_logits_mma<<<dim3((B * TT) / 128, V / 128), 256>>>(out);
}

// round 6
// speedup vs baseline: 2.2991x; 1.2207x over previous
#include <cuda_runtime.h>
#include <cuda_bf16.h>
#include <math.h>
#include <stdint.h>

#define B  32
#define LX 64
#define TT 64
#define D  1024
#define V  32000
#define KP 3072
#define GRIDN 128

// ------------------- device globals (no allocation) ---------------------------
__device__ float g_c[B * D];
__device__ float g_gatesp2[4 * 64 * 4096];     // gates partials [split][64][4096]
__device__ float g_hprojp2[16 * 64 * 1024];    // hproj partials
__device__ float g_prep2[16 * 64 * 1024];      // pre partials
__device__ __align__(16) __nv_bfloat16 g_A2g[64 * 8192];           // gates A2
__device__ __align__(16) __nv_bfloat16 g_A2h[64 * 2048];           // hproj A2
__device__ __align__(16) __nv_bfloat16 g_A2p[64 * 6144];           // pre A2
__device__ __align__(16) __nv_bfloat16 g_Abf[(TT * B) * KP];       // logits A'
__device__ __align__(16) __nv_bfloat16 g_Bbf[(size_t)V * KP];      // logits B'
__device__ __align__(16) __nv_bfloat16 g_Wg2[(size_t)4096 * 8192]; // gates W2
__device__ __align__(16) __nv_bfloat16 g_Wh2[1024 * 2048];         // hproj W2
__device__ __align__(16) __nv_bfloat16 g_Wp2[1024 * 6144];         // pre W2
__device__ unsigned g_arrive;
__device__ volatile unsigned g_release;

// ------------------- helpers ---------------------------------------------------
__device__ __forceinline__ float fast_tanh(float x) {
    float e = __expf(2.f * x);
    return 1.f - __fdividef(2.f, e + 1.f);
}
__device__ __forceinline__ uint32_t smem_u32(const void* p) {
    uint32_t a;
    asm("{ .reg .u64 t; cvta.to.shared.u64 t, %1; cvt.u32.u64 %0, t; }" : "=r"(a) : "l"(p));
    return a;
}
__device__ __forceinline__ void cpasync16(uint32_t dst, const void* src) {
    asm volatile("cp.async.cg.shared.global [%0], [%1], 16;" :: "r"(dst), "l"(src));
}
__device__ __forceinline__ void ldm_x4(uint32_t* r, uint32_t addr) {
    asm volatile("ldmatrix.sync.aligned.m8n8.x4.shared.b16 {%0,%1,%2,%3}, [%4];"
        : "=r"(r[0]), "=r"(r[1]), "=r"(r[2]), "=r"(r[3]) : "r"(addr));
}
__device__ __forceinline__ void mma_bf16(float* c, const uint32_t* a, const uint32_t* b) {
    asm volatile("mma.sync.aligned.m16n8k16.row.col.f32.bf16.bf16.f32 "
        "{%0,%1,%2,%3}, {%4,%5,%6,%7}, {%8,%9}, {%0,%1,%2,%3};"
        : "+f"(c[0]), "+f"(c[1]), "+f"(c[2]), "+f"(c[3])
        : "r"(a[0]), "r"(a[1]), "r"(a[2]), "r"(a[3]), "r"(b[0]), "r"(b[1]));
}
__device__ __forceinline__ void split_bf(float v, __nv_bfloat16& hi, __nv_bfloat16& lo) {
    hi = __float2bfloat16_rn(v);
    lo = __float2bfloat16_rn(v - __bfloat162float(hi));
}

// ------------------- grid barrier ------------------------------------------------
__device__ __forceinline__ void gridbar(unsigned gen) {
    __threadfence();
    __syncthreads();
    if (threadIdx.x == 0) {
        unsigned a = atomicAdd(&g_arrive, 1u) + 1u;
        if (a == gen * GRIDN) {
            atomicExch((unsigned*)&g_release, gen);
        } else {
            while (g_release < gen) __nanosleep(32);
        }
    }
    __syncthreads();
}

// ------------------- init: state + A2 buffers ------------------------------------
__global__ void k_init0(const float* __restrict__ h0, const float* __restrict__ c0,
                        const float* __restrict__ word_emb,
                        const int* __restrict__ y_train) {
    int i = blockIdx.x * 256 + threadIdx.x;
    if (i == 0) { g_arrive = 0; g_release = 0; }
    // region 1: full gates A2 for t=0 (64 x 8192)
    if (i < 64 * 8192) {
        int r = i >> 13, k = i & 8191;
        int b = r & 31;
        bool isLo = r >= 32;
        int ks = (k < 4096) ? k : k - 4096;
        float v = 0.f;
        bool zero = (isLo && k >= 4096);
        if (!zero) {
            if (ks < 1024) {
                int y = y_train[b * TT + 0];
                v = word_emb[(size_t)y * D + ks];
            } else if (ks < 3072) {
                v = 0.f;                       // feed(0) = 0
            } else {
                v = h0[b * D + (ks - 3072)];
            }
        }
        __nv_bfloat16 hi, lo; split_bf(v, hi, lo);
        g_A2g[i] = zero ? __float2bfloat16_rn(0.f) : (isLo ? lo : hi);
        return;
    }
    int j = i - 64 * 8192;
    // region 2: hproj A2 zero block rows 32-63, k [1024,2048)
    if (j < 32 * 1024) {
        int r = 32 + (j >> 10), k = 1024 + (j & 1023);
        g_A2h[r * 2048 + k] = __float2bfloat16_rn(0.f);
        return;
    }
    j -= 32 * 1024;
    // region 3: pre A2 zero block rows 32-63, k [3072,6144)
    if (j < 32 * 3072) {
        int r = 32 + j / 3072, k = 3072 + j % 3072;
        g_A2p[r * 6144 + k] = __float2bfloat16_rn(0.f);
        return;
    }
    j -= 32 * 3072;
    // region 4: c state
    if (j < B * D) g_c[j] = c0[j];
}

// ------------------- weight conversions -------------------------------------------
__global__ void k_convB(const float* __restrict__ RW) {
    int i = blockIdx.x * 256 + threadIdx.x;     // < V*D
    float v = RW[i];
    int r = i >> 10, d = i & 1023;
    __nv_bfloat16 hi, lo; split_bf(v, hi, lo);
    __nv_bfloat16* row = g_Bbf + (size_t)r * KP;
    row[d] = hi; row[1024 + d] = hi; row[2048 + d] = lo;
}
__global__ void k_convWg(const float* __restrict__ Wih, const float* __restrict__ Whh) {
    int k = blockIdx.x * 256 + threadIdx.x;     // 0..4095
    int j = blockIdx.y;                          // 0..4095
    float v = (k < 3072) ? Wih[(size_t)j * 3072 + k] : Whh[(size_t)j * 1024 + (k - 3072)];
    __nv_bfloat16 hi, lo; split_bf(v, hi, lo);
    g_Wg2[(size_t)j * 8192 + k] = hi;
    g_Wg2[(size_t)j * 8192 + 4096 + k] = lo;
}
__global__ void k_convWh(const float* __restrict__ Wt) {
    int k = blockIdx.x * 256 + threadIdx.x;
    int j = blockIdx.y;
    float v = Wt[(size_t)j * 1024 + k];
    __nv_bfloat16 hi, lo; split_bf(v, hi, lo);
    g_Wh2[j * 2048 + k] = hi;
    g_Wh2[j * 2048 + 1024 + k] = lo;
}
__global__ void k_convWp(const float* __restrict__ Cw) {
    int k = blockIdx.x * 256 + threadIdx.x;     // 0..3071
    int j = blockIdx.y;
    float v = Cw[(size_t)j * 3072 + k];
    __nv_bfloat16 hi, lo; split_bf(v, hi, lo);
    g_Wp2[j * 6144 + k] = hi;
    g_Wp2[j * 6144 + 3072 + k] = lo;
}

// ------------------- pipelined 64xK @ Kx128 MMA phase -----------------------------
// smem layout (46080 B static): A stages 3x5120 @0, B stages 3x10240 @15360
#define ABASE 0
#define BBASE 15360

__device__ __forceinline__ void phase_load(uint32_t sb, const __nv_bfloat16* __restrict__ A2,
                                           const __nv_bfloat16* __restrict__ B2,
                                           int K2, int kb, int col0, int st, int tid) {
    int ar = tid >> 2, ali = tid & 3;
    cpasync16(sb + ABASE + st * 5120 + ar * 80 + ali * 16,
              A2 + (size_t)ar * K2 + kb + ali * 8);
#pragma unroll
    for (int q = 0; q < 2; q++) {
        int idx = q * 256 + tid;
        int br = idx >> 2, bli = idx & 3;
        cpasync16(sb + BBASE + st * 10240 + br * 80 + bli * 16,
                  B2 + (size_t)(col0 + br) * K2 + kb + bli * 8);
    }
    asm volatile("cp.async.commit_group;" ::: "memory");
}

__device__ void mma_phase3(uint32_t sb, const __nv_bfloat16* __restrict__ A2,
                           const __nv_bfloat16* __restrict__ B2,
                           float* __restrict__ part,
                           int ncols, int K2, int nch, int col0, int split) {
    int tid = threadIdx.x;
    int lane = tid & 31, wid = tid >> 5;
    int warpM = wid & 1, warpN = wid >> 1;
    int kbase0 = split * nch * 32;

    int a_row = (lane & 7) + ((lane >> 3) & 1) * 8;
    int a_k   = (lane >> 4) * 8;
    int b_row = (lane & 7) + (lane >> 4) * 8;
    int b_k   = ((lane >> 3) & 1) * 8;
    uint32_t aB = sb + ABASE + ((warpM * 32 + a_row) * 40 + a_k) * 2;
    uint32_t bB = sb + BBASE + ((warpN * 32 + b_row) * 40 + b_k) * 2;

    float acc[2][4][4];
#pragma unroll
    for (int a = 0; a < 2; a++)
#pragma unroll
        for (int b = 0; b < 4; b++)
#pragma unroll
            for (int q = 0; q < 4; q++) acc[a][b][q] = 0.f;

    // prologue: chunks 0,1
    phase_load(sb, A2, B2, K2, kbase0, col0, 0, tid);
    if (nch > 1) phase_load(sb, A2, B2, K2, kbase0 + 32, col0, 1, tid);

    for (int i = 0; i < nch; i++) {
        int st = i % 3;
        if (i + 1 < nch) {
            asm volatile("cp.async.wait_group 1;" ::: "memory");
        } else {
            asm volatile("cp.async.wait_group 0;" ::: "memory");
        }
        __syncthreads();
        if (i + 2 < nch)
            phase_load(sb, A2, B2, K2, kbase0 + (i + 2) * 32, col0, (i + 2) % 3, tid);

#pragma unroll
        for (int k16 = 0; k16 < 2; k16++) {
            uint32_t ao = st * 5120u  + k16 * 32u;
            uint32_t bo = st * 10240u + k16 * 32u;
            uint32_t a0[4], a1[4], bb[2][4];
            ldm_x4(a0, aB + ao);
            ldm_x4(a1, aB + ao + 1280);
            ldm_x4(bb[0], bB + bo);
            ldm_x4(bb[1], bB + bo + 1280);
#pragma unroll
            for (int nt = 0; nt < 4; nt++) {
                mma_bf16(acc[0][nt], a0, &bb[nt >> 1][(nt & 1) * 2]);
                mma_bf16(acc[1][nt], a1, &bb[nt >> 1][(nt & 1) * 2]);
            }
        }
    }

    // epilogue → partials
    int grp = lane >> 2, tig = lane & 3;
#pragma unroll
    for (int mt = 0; mt < 2; mt++) {
        int m1 = warpM * 32 + mt * 16 + grp;
        int m2 = m1 + 8;
        float* p1 = part + (size_t)(split * 64 + m1) * ncols + col0 + warpN * 32;
        float* p2 = part + (size_t)(split * 64 + m2) * ncols + col0 + warpN * 32;
#pragma unroll
        for (int nt = 0; nt < 4; nt++) {
            int n = nt * 8 + tig * 2;
            *(float2*)(p1 + n) = make_float2(acc[mt][nt][0], acc[mt][nt][1]);
            *(float2*)(p2 + n) = make_float2(acc[mt][nt][2], acc[mt][nt][3]);
        }
    }
}

// ------------------- per-phase scalar work -----------------------------------------
__device__ void cell_work(int bid, const float* __restrict__ b_ih,
                          const float* __restrict__ b_hh) {
    int id = bid * 256 + threadIdx.x;           // 0..32767
    int m = id >> 10, d = id & 1023;
    float ig = b_ih[d]        + b_hh[d];
    float fg = b_ih[1024 + d] + b_hh[1024 + d];
    float gg = b_ih[2048 + d] + b_hh[2048 + d];
    float og = b_ih[3072 + d] + b_hh[3072 + d];
#pragma unroll
    for (int s = 0; s < 4; s++) {
        const float* p0 = g_gatesp2 + (size_t)(s * 64 + m) * 4096;
        const float* p1 = g_gatesp2 + (size_t)(s * 64 + 32 + m) * 4096;
        ig += __ldcg(p0 + d)        + __ldcg(p1 + d);
        fg += __ldcg(p0 + 1024 + d) + __ldcg(p1 + 1024 + d);
        gg += __ldcg(p0 + 2048 + d) + __ldcg(p1 + 2048 + d);
        og += __ldcg(p0 + 3072 + d) + __ldcg(p1 + 3072 + d);
    }
    float si = 1.f / (1.f + expf(-ig));
    float sf = 1.f / (1.f + expf(-fg));
    float so = 1.f / (1.f + expf(-og));
    float c = sf * __ldcg(&g_c[id]) + si * tanhf(gg);
    g_c[id] = c;
    float h = so * tanhf(c);
    __nv_bfloat16 hh, hl; split_bf(h, hh, hl);
    // hproj A2 [64][2048]
    g_A2h[m * 2048 + d] = hh;
    g_A2h[m * 2048 + 1024 + d] = hh;
    g_A2h[(32 + m) * 2048 + d] = hl;
    // pre A2 [64][6144]
    g_A2p[m * 6144 + d] = hh;
    g_A2p[m * 6144 + 3072 + d] = hh;
    g_A2p[(32 + m) * 6144 + d] = hl;
    // gates A2 [64][8192]: h at ks 3072..4096
    g_A2g[m * 8192 + 3072 + d] = hh;
    g_A2g[m * 8192 + 7168 + d] = hh;
    g_A2g[(32 + m) * 8192 + 3072 + d] = hl;
}

__device__ void pretanh_work(int t, int bid) {
    int id = bid * 256 + threadIdx.x;           // 0..32767
    int m = id >> 10, d = id & 1023;
    float v = 0.f;
#pragma unroll
    for (int s = 0; s < 16; s++) {
        v += __ldcg(&g_prep2[(size_t)(s * 64 + m) * 1024 + d]);
        v += __ldcg(&g_prep2[(size_t)(s * 64 + 32 + m) * 1024 + d]);
    }
    v = tanhf(v);
    int row = t * B + m;
    __nv_bfloat16 hi, lo; split_bf(v, hi, lo);
    __nv_bfloat16* arow = g_Abf + (size_t)row * KP;
    arow[d] = hi; arow[1024 + d] = lo; arow[2048 + d] = hi;
}

__device__ void attn_work(int b, float* s_hp, float* s_wl,
                          const float* __restrict__ x_enc,
                          const float* __restrict__ x_enc_k,
                          const unsigned char* __restrict__ xm,
                          const float* __restrict__ w_trg_b,
                          const float* __restrict__ w_att,
                          const float* __restrict__ w_att_b) {
    int tid = threadIdx.x;
    int lane = tid & 31, wd = tid >> 5;
    for (int d = tid; d < 1024; d += 256) {
        float sum = w_trg_b[d];
#pragma unroll
        for (int s = 0; s < 16; s++) {
            sum += __ldcg(&g_hprojp2[(size_t)(s * 64 + b) * 1024 + d]);
            sum += __ldcg(&g_hprojp2[(size_t)(s * 64 + 32 + b) * 1024 + d]);
        }
        s_hp[d] = sum;
    }
    __syncthreads();
    for (int l = wd; l < LX; l += 8) {
        const float* xk = x_enc_k + ((size_t)b * LX + l) * D;
        float s = 0.f;
#pragma unroll 8
        for (int i = 0; i < 32; i++) {
            int d = lane + i * 32;
            s += fast_tanh(xk[d] + s_hp[d]) * w_att[d];
        }
#pragma unroll
        for (int off = 16; off; off >>= 1) s += __shfl_xor_sync(0xffffffffu, s, off);
        if (lane == 0) {
            float tot = s + w_att_b[0];
            if (xm[b * LX + l]) tot = -1e9f;
            s_wl[l] = tot;
        }
    }
    __syncthreads();
    if (tid == 0) {
        float mx = -1e30f;
        for (int l = 0; l < LX; l++) mx = fmaxf(mx, s_wl[l]);
        float z = 0.f;
        for (int l = 0; l < LX; l++) { float e = expf(s_wl[l] - mx); s_wl[l] = e; z += e; }
        float inv = 1.f / z;
        for (int l = 0; l < LX; l++) s_wl[l] *= inv;
    }
    __syncthreads();
    {
        int d2 = tid * 8;
        const float* xe = x_enc + (size_t)b * LX * 2048 + d2;
        float f[8];
#pragma unroll
        for (int q = 0; q < 8; q++) f[q] = 0.f;
#pragma unroll 8
        for (int l = 0; l < LX; l++) {
            float w = s_wl[l];
            float4 x0 = *(const float4*)(xe + (size_t)l * 2048);
            float4 x1 = *(const float4*)(xe + (size_t)l * 2048 + 4);
            f[0] += w * x0.x; f[1] += w * x0.y; f[2] += w * x0.z; f[3] += w * x0.w;
            f[4] += w * x1.x; f[5] += w * x1.y; f[6] += w * x1.z; f[7] += w * x1.w;
        }
#pragma unroll
        for (int q = 0; q < 8; q++) {
            int dd = 1024 + d2 + q;             // ks position of feed
            __nv_bfloat16 hi, lo; split_bf(f[q], hi, lo);
            g_A2p[b * 6144 + dd] = hi;
            g_A2p[b * 6144 + 3072 + dd] = hi;
            g_A2p[(32 + b) * 6144 + dd] = lo;
            g_A2g[b * 8192 + dd] = hi;
            g_A2g[b * 8192 + 4096 + dd] = hi;
            g_A2g[(32 + b) * 8192 + dd] = lo;
        }
    }
}

__device__ void emb_prefetch(int b, int tnext, const float* __restrict__ word_emb,
                             const int* __restrict__ y_train) {
    int d = threadIdx.x * 4;
    int y = y_train[b * TT + tnext];
    float4 v = *(const float4*)(word_emb + (size_t)y * D + d);
    float vv[4] = {v.x, v.y, v.z, v.w};
#pragma unroll
    for (int q = 0; q < 4; q++) {
        __nv_bfloat16 hi, lo; split_bf(vv[q], hi, lo);
        int k = d + q;
        g_A2g[b * 8192 + k] = hi;
        g_A2g[b * 8192 + 4096 + k] = hi;
        g_A2g[(32 + b) * 8192 + k] = lo;
    }
}

// ------------------- persistent step kernel ----------------------------------------
__global__ void __launch_bounds__(256, 1) k_steps(
    const float* __restrict__ x_enc, const float* __restrict__ x_enc_k,
    const unsigned char* __restrict__ xm, const int* __restrict__ y_train,
    const float* __restrict__ word_emb,
    const float* __restrict__ b_ih, const float* __restrict__ b_hh,
    const float* __restrict__ w_trg_b, const float* __restrict__ w_att,
    const float* __restrict__ w_att_b) {
    __shared__ __align__(16) char s_raw[46080];
    uint32_t sb = smem_u32(s_raw);
    float* s_hp = (float*)s_raw;            // attn overlay (phase 4 only)
    float* s_wl = (float*)(s_raw + 4096);
    int bid = blockIdx.x;
    unsigned gen = 0;

    for (int t = 0; t < TT; t++) {
        // phase 1: pretanh(t-1) + gates MMA
        if (t > 0) pretanh_work(t - 1, bid);
        mma_phase3(sb, g_A2g, g_Wg2, g_gatesp2, 4096, 8192, 64,
                   (bid & 31) * 128, bid >> 5);
        gridbar(++gen);
        // phase 2: LSTM cell (+ writes h2 into all A2 buffers)
        cell_work(bid, b_ih, b_hh);
        gridbar(++gen);
        // phase 3: hproj MMA
        mma_phase3(sb, g_A2h, g_Wh2, g_hprojp2, 1024, 2048, 4,
                   (bid & 7) * 128, bid >> 3);
        gridbar(++gen);
        // phase 4: attention (CTAs 0-31) + emb(t+1) prefetch (CTAs 32-63)
        if (bid < 32)
            attn_work(bid, s_hp, s_wl, x_enc, x_enc_k, xm, w_trg_b, w_att, w_att_b);
        else if (bid < 64 && t + 1 < TT)
            emb_prefetch(bid - 32, t + 1, word_emb, y_train);
        gridbar(++gen);
        // phase 5: pre MMA
        mma_phase3(sb, g_A2p, g_Wp2, g_prep2, 1024, 6144, 12,
                   (bid & 7) * 128, bid >> 3);
        gridbar(++gen);
    }
    pretanh_work(TT - 1, bid);
}

// ------------------- logits GEMM via mma.sync (unchanged, passing) ------------------
__global__ void __launch_bounds__(256, 2) k_logits_mma(float* __restrict__ out) {
    __shared__ __align__(16) __nv_bfloat16 sA[2][128][40];
    __shared__ __align__(16) __nv_bfloat16 sB[2][128][40];
    int tid = threadIdx.x;
    int lane = tid & 31, wid = tid >> 5;
    int warpM = wid & 1, warpN = wid >> 1;
    int row0 = blockIdx.x * 128;
    int col0 = blockIdx.y * 128;

    int a_row = (lane & 7) + ((lane >> 3) & 1) * 8;
    int a_k   = (lane >> 4) * 8;
    int b_row = (lane & 7) + (lane >> 4) * 8;
    int b_k   = ((lane >> 3) & 1) * 8;
    uint32_t aBase = smem_u32(&sA[0][0][0]) + (warpM * 64 + a_row) * 80 + a_k * 2;
    uint32_t bBase = smem_u32(&sB[0][0][0]) + (warpN * 32 + b_row) * 80 + b_k * 2;

    int ldr = tid >> 2;
    int ldi = tid & 3;

    float acc[4][4][4];
#pragma unroll
    for (int i = 0; i < 4; i++)
#pragma unroll
        for (int j = 0; j < 4; j++)
#pragma unroll
            for (int q = 0; q < 4; q++) acc[i][j][q] = 0.f;

#pragma unroll
    for (int q = 0; q < 2; q++) {
        int r = ldr + q * 64;
        cpasync16(smem_u32(&sA[0][r][ldi * 8]), g_Abf + (size_t)(row0 + r) * KP + ldi * 8);
        cpasync16(smem_u32(&sB[0][r][ldi * 8]), g_Bbf + (size_t)(col0 + r) * KP + ldi * 8);
    }
    asm volatile("cp.async.commit_group;" ::: "memory");

    const int NCH = KP / 32;
    for (int i = 0; i < NCH; i++) {
        int st = i & 1;
        if (i + 1 < NCH) {
            int ns = st ^ 1;
            int kb = (i + 1) * 32;
#pragma unroll
            for (int q = 0; q < 2; q++) {
                int r = ldr + q * 64;
                cpasync16(smem_u32(&sA[ns][r][ldi * 8]),
                          g_Abf + (size_t)(row0 + r) * KP + kb + ldi * 8);
                cpasync16(smem_u32(&sB[ns][r][ldi * 8]),
                          g_Bbf + (size_t)(col0 + r) * KP + kb + ldi * 8);
            }
            asm volatile("cp.async.commit_group;" ::: "memory");
            asm volatile("cp.async.wait_group 1;" ::: "memory");
        } else {
            asm volatile("cp.async.wait_group 0;" ::: "memory");
        }
        __syncthreads();

        uint32_t stoff = st * (uint32_t)(128 * 80);
#pragma unroll
        for (int k16 = 0; k16 < 2; k16++) {
            uint32_t koff = stoff + k16 * 32;
            uint32_t a[4][4], b[2][4];
#pragma unroll
            for (int mt = 0; mt < 4; mt++) ldm_x4(a[mt], aBase + koff + mt * 1280);
#pragma unroll
            for (int p = 0; p < 2; p++)    ldm_x4(b[p], bBase + koff + p * 1280);
#pragma unroll
            for (int mt = 0; mt < 4; mt++)
#pragma unroll
                for (int nt = 0; nt < 4; nt++)
                    mma_bf16(acc[mt][nt], a[mt], &b[nt >> 1][(nt & 1) * 2]);
        }
        __syncthreads();
    }

    int grp = lane >> 2, tig = lane & 3;
#pragma unroll
    for (int mt = 0; mt < 4; mt++) {
        int m1 = row0 + warpM * 64 + mt * 16 + grp;
        int m2 = m1 + 8;
        float* o1 = out + ((size_t)(m1 & 31) * TT + (m1 >> 5)) * V;
        float* o2 = out + ((size_t)(m2 & 31) * TT + (m2 >> 5)) * V;
#pragma unroll
        for (int nt = 0; nt < 4; nt++) {
            int n = col0 + warpN * 32 + nt * 8 + tig * 2;
            *(float2*)(o1 + n) = make_float2(acc[mt][nt][0], acc[mt][nt][1]);
            *(float2*)(o2 + n) = make_float2(acc[mt][nt][2], acc[mt][nt][3]);
        }
    }
}

// ------------------- launch ----------------------------------------------------------
extern "C" void kernel_launch(void* const* d_in, const int* in_sizes, int n_in,
                              void* d_out, int out_size) {
    const float* x_enc      = (const float*)d_in[0];
    const float* x_enc_k    = (const float*)d_in[1];
    const float* h0         = (const float*)d_in[2];
    const float* c0         = (const float*)d_in[3];
    const unsigned char* xm = (const unsigned char*)d_in[4];
    const int*   y_train    = (const int*)d_in[5];
    const float* word_emb   = (const float*)d_in[6];
    const float* W_ih       = (const float*)d_in[7];
    const float* W_hh       = (const float*)d_in[8];
    const float* b_ih       = (const float*)d_in[9];
    const float* b_hh       = (const float*)d_in[10];
    const float* w_trg_W    = (const float*)d_in[11];
    const float* w_trg_b    = (const float*)d_in[12];
    const float* w_att      = (const float*)d_in[13];
    const float* w_att_b    = (const float*)d_in[14];
    const float* ctx_W      = (const float*)d_in[15];
    const float* RW         = (const float*)d_in[16];
    float* out = (float*)d_out;

    k_convB<<<(V * D) / 256, 256>>>(RW);
    k_convWg<<<dim3(16, 4096), 256>>>(W_ih, W_hh);
    k_convWh<<<dim3(4, 1024), 256>>>(w_trg_W);
    k_convWp<<<dim3(12, 1024), 256>>>(ctx_W);
    // init covers A2g full + A2h/A2p zero blocks + c0: 64*8192 + 32*1024 + 32*3072 + 32*1024
    int init_total = 64 * 8192 + 32 * 1024 + 32 * 3072 + B * D;
    k_init0<<<(init_total + 255) / 256, 256>>>(h0, c0, word_emb, y_train);
    k_steps<<<GRIDN, 256>>>(x_enc, x_enc_k, xm, y_train, word_emb,
                            b_ih, b_hh, w_trg_b, w_att, w_att_b);
    k_logits_mma<<<dim3((B * TT) / 128, V / 128), 256>>>(out);
}

// round 7
// speedup vs baseline: 2.3129x; 1.0060x over previous
#include <cuda_runtime.h>
#include <cuda_bf16.h>
#include <math.h>
#include <stdint.h>

#define B  32
#define LX 64
#define TT 64
#define D  1024
#define V  32000
#define KP 3072
#define GRIDN 128

// ------------------- device globals (no allocation) ---------------------------
__device__ float g_c[B * D];
__device__ float g_gatesp2[4 * 64 * 4096];     // gates partials [split][64][4096]
__device__ float g_hprojp2[16 * 64 * 1024];    // hproj partials
__device__ float g_prep2[16 * 64 * 1024];      // pre partials
__device__ __align__(16) __nv_bfloat16 g_A2g[64 * 8192];           // gates A2
__device__ __align__(16) __nv_bfloat16 g_A2h[64 * 2048];           // hproj A2
__device__ __align__(16) __nv_bfloat16 g_A2p[64 * 6144];           // pre A2
__device__ __align__(16) __nv_bfloat16 g_Abf[(TT * B) * KP];       // logits A'
__device__ __align__(16) __nv_bfloat16 g_Bbf[(size_t)V * KP];      // logits B'
__device__ __align__(16) __nv_bfloat16 g_Wg2[(size_t)4096 * 8192]; // gates W2
__device__ __align__(16) __nv_bfloat16 g_Wh2[1024 * 2048];         // hproj W2
__device__ __align__(16) __nv_bfloat16 g_Wp2[1024 * 6144];         // pre W2
__device__ unsigned g_arrive;
__device__ volatile unsigned g_release;

// ------------------- helpers ---------------------------------------------------
__device__ __forceinline__ float fast_tanh(float x) {
    float e = __expf(2.f * x);
    return 1.f - __fdividef(2.f, e + 1.f);
}
__device__ __forceinline__ uint32_t smem_u32(const void* p) {
    uint32_t a;
    asm("{ .reg .u64 t; cvta.to.shared.u64 t, %1; cvt.u32.u64 %0, t; }" : "=r"(a) : "l"(p));
    return a;
}
__device__ __forceinline__ void cpasync16(uint32_t dst, const void* src) {
    asm volatile("cp.async.cg.shared.global [%0], [%1], 16;" :: "r"(dst), "l"(src));
}
__device__ __forceinline__ void ldm_x4(uint32_t* r, uint32_t addr) {
    asm volatile("ldmatrix.sync.aligned.m8n8.x4.shared.b16 {%0,%1,%2,%3}, [%4];"
        : "=r"(r[0]), "=r"(r[1]), "=r"(r[2]), "=r"(r[3]) : "r"(addr));
}
__device__ __forceinline__ void mma_bf16(float* c, const uint32_t* a, const uint32_t* b) {
    asm volatile("mma.sync.aligned.m16n8k16.row.col.f32.bf16.bf16.f32 "
        "{%0,%1,%2,%3}, {%4,%5,%6,%7}, {%8,%9}, {%0,%1,%2,%3};"
        : "+f"(c[0]), "+f"(c[1]), "+f"(c[2]), "+f"(c[3])
        : "r"(a[0]), "r"(a[1]), "r"(a[2]), "r"(a[3]), "r"(b[0]), "r"(b[1]));
}
__device__ __forceinline__ void split_bf(float v, __nv_bfloat16& hi, __nv_bfloat16& lo) {
    hi = __float2bfloat16_rn(v);
    lo = __float2bfloat16_rn(v - __bfloat162float(hi));
}

// ------------------- grid barrier ------------------------------------------------
__device__ __forceinline__ void gridbar(unsigned gen) {
    __threadfence();
    __syncthreads();
    if (threadIdx.x == 0) {
        unsigned a = atomicAdd(&g_arrive, 1u) + 1u;
        if (a == gen * GRIDN) {
            atomicExch((unsigned*)&g_release, gen);
        } else {
            while (g_release < gen) __nanosleep(32);
        }
    }
    __syncthreads();
}

// ------------------- init: state + A2 buffers ------------------------------------
__global__ void k_init0(const float* __restrict__ h0, const float* __restrict__ c0,
                        const float* __restrict__ word_emb,
                        const int* __restrict__ y_train) {
    int i = blockIdx.x * 256 + threadIdx.x;
    if (i == 0) { g_arrive = 0; g_release = 0; }
    // region 1: full gates A2 for t=0 (64 x 8192)
    if (i < 64 * 8192) {
        int r = i >> 13, k = i & 8191;
        int b = r & 31;
        bool isLo = r >= 32;
        int ks = (k < 4096) ? k : k - 4096;
        float v = 0.f;
        bool zero = (isLo && k >= 4096);
        if (!zero) {
            if (ks < 1024) {
                int y = y_train[b * TT + 0];
                v = word_emb[(size_t)y * D + ks];
            } else if (ks < 3072) {
                v = 0.f;                       // feed(0) = 0
            } else {
                v = h0[b * D + (ks - 3072)];
            }
        }
        __nv_bfloat16 hi, lo; split_bf(v, hi, lo);
        g_A2g[i] = zero ? __float2bfloat16_rn(0.f) : (isLo ? lo : hi);
        return;
    }
    int j = i - 64 * 8192;
    // region 2: hproj A2 zero block rows 32-63, k [1024,2048)
    if (j < 32 * 1024) {
        int r = 32 + (j >> 10), k = 1024 + (j & 1023);
        g_A2h[r * 2048 + k] = __float2bfloat16_rn(0.f);
        return;
    }
    j -= 32 * 1024;
    // region 3: pre A2 zero block rows 32-63, k [3072,6144)
    if (j < 32 * 3072) {
        int r = 32 + j / 3072, k = 3072 + j % 3072;
        g_A2p[r * 6144 + k] = __float2bfloat16_rn(0.f);
        return;
    }
    j -= 32 * 3072;
    // region 4: c state
    if (j < B * D) g_c[j] = c0[j];
}

// ------------------- weight conversions -------------------------------------------
__global__ void k_convB(const float* __restrict__ RW) {
    int i = blockIdx.x * 256 + threadIdx.x;     // < V*D
    float v = RW[i];
    int r = i >> 10, d = i & 1023;
    __nv_bfloat16 hi, lo; split_bf(v, hi, lo);
    __nv_bfloat16* row = g_Bbf + (size_t)r * KP;
    row[d] = hi; row[1024 + d] = hi; row[2048 + d] = lo;
}
__global__ void k_convWg(const float* __restrict__ Wih, const float* __restrict__ Whh) {
    int k = blockIdx.x * 256 + threadIdx.x;     // 0..4095
    int j = blockIdx.y;                          // 0..4095
    float v = (k < 3072) ? Wih[(size_t)j * 3072 + k] : Whh[(size_t)j * 1024 + (k - 3072)];
    __nv_bfloat16 hi, lo; split_bf(v, hi, lo);
    g_Wg2[(size_t)j * 8192 + k] = hi;
    g_Wg2[(size_t)j * 8192 + 4096 + k] = lo;
}
__global__ void k_convWh(const float* __restrict__ Wt) {
    int k = blockIdx.x * 256 + threadIdx.x;
    int j = blockIdx.y;
    float v = Wt[(size_t)j * 1024 + k];
    __nv_bfloat16 hi, lo; split_bf(v, hi, lo);
    g_Wh2[j * 2048 + k] = hi;
    g_Wh2[j * 2048 + 1024 + k] = lo;
}
__global__ void k_convWp(const float* __restrict__ Cw) {
    int k = blockIdx.x * 256 + threadIdx.x;     // 0..3071
    int j = blockIdx.y;
    float v = Cw[(size_t)j * 3072 + k];
    __nv_bfloat16 hi, lo; split_bf(v, hi, lo);
    g_Wp2[j * 6144 + k] = hi;
    g_Wp2[j * 6144 + 3072 + k] = lo;
}

// ------------------- pipelined 64xK @ Kx128 MMA phase -----------------------------
// smem layout (46080 B static): A stages 3x5120 @0, B stages 3x10240 @15360
#define ABASE 0
#define BBASE 15360

__device__ __forceinline__ void phase_load(uint32_t sb, const __nv_bfloat16* __restrict__ A2,
                                           const __nv_bfloat16* __restrict__ B2,
                                           int K2, int kb, int col0, int st, int tid) {
    int ar = tid >> 2, ali = tid & 3;
    cpasync16(sb + ABASE + st * 5120 + ar * 80 + ali * 16,
              A2 + (size_t)ar * K2 + kb + ali * 8);
#pragma unroll
    for (int q = 0; q < 2; q++) {
        int idx = q * 256 + tid;
        int br = idx >> 2, bli = idx & 3;
        cpasync16(sb + BBASE + st * 10240 + br * 80 + bli * 16,
                  B2 + (size_t)(col0 + br) * K2 + kb + bli * 8);
    }
    asm volatile("cp.async.commit_group;" ::: "memory");
}

__device__ void mma_phase3(uint32_t sb, const __nv_bfloat16* __restrict__ A2,
                           const __nv_bfloat16* __restrict__ B2,
                           float* __restrict__ part,
                           int ncols, int K2, int nch, int col0, int split) {
    int tid = threadIdx.x;
    int lane = tid & 31, wid = tid >> 5;
    int warpM = wid & 1, warpN = wid >> 1;
    int kbase0 = split * nch * 32;

    int a_row = (lane & 7) + ((lane >> 3) & 1) * 8;
    int a_k   = (lane >> 4) * 8;
    int b_row = (lane & 7) + (lane >> 4) * 8;
    int b_k   = ((lane >> 3) & 1) * 8;
    uint32_t aB = sb + ABASE + ((warpM * 32 + a_row) * 40 + a_k) * 2;
    uint32_t bB = sb + BBASE + ((warpN * 32 + b_row) * 40 + b_k) * 2;

    float acc[2][4][4];
#pragma unroll
    for (int a = 0; a < 2; a++)
#pragma unroll
        for (int b = 0; b < 4; b++)
#pragma unroll
            for (int q = 0; q < 4; q++) acc[a][b][q] = 0.f;

    // prologue: chunks 0,1
    phase_load(sb, A2, B2, K2, kbase0, col0, 0, tid);
    if (nch > 1) phase_load(sb, A2, B2, K2, kbase0 + 32, col0, 1, tid);

    for (int i = 0; i < nch; i++) {
        int st = i % 3;
        if (i + 1 < nch) {
            asm volatile("cp.async.wait_group 1;" ::: "memory");
        } else {
            asm volatile("cp.async.wait_group 0;" ::: "memory");
        }
        __syncthreads();
        if (i + 2 < nch)
            phase_load(sb, A2, B2, K2, kbase0 + (i + 2) * 32, col0, (i + 2) % 3, tid);

#pragma unroll
        for (int k16 = 0; k16 < 2; k16++) {
            uint32_t ao = st * 5120u  + k16 * 32u;
            uint32_t bo = st * 10240u + k16 * 32u;
            uint32_t a0[4], a1[4], bb[2][4];
            ldm_x4(a0, aB + ao);
            ldm_x4(a1, aB + ao + 1280);
            ldm_x4(bb[0], bB + bo);
            ldm_x4(bb[1], bB + bo + 1280);
#pragma unroll
            for (int nt = 0; nt < 4; nt++) {
                mma_bf16(acc[0][nt], a0, &bb[nt >> 1][(nt & 1) * 2]);
                mma_bf16(acc[1][nt], a1, &bb[nt >> 1][(nt & 1) * 2]);
            }
        }
    }

    // epilogue → partials
    int grp = lane >> 2, tig = lane & 3;
#pragma unroll
    for (int mt = 0; mt < 2; mt++) {
        int m1 = warpM * 32 + mt * 16 + grp;
        int m2 = m1 + 8;
        float* p1 = part + (size_t)(split * 64 + m1) * ncols + col0 + warpN * 32;
        float* p2 = part + (size_t)(split * 64 + m2) * ncols + col0 + warpN * 32;
#pragma unroll
        for (int nt = 0; nt < 4; nt++) {
            int n = nt * 8 + tig * 2;
            *(float2*)(p1 + n) = make_float2(acc[mt][nt][0], acc[mt][nt][1]);
            *(float2*)(p2 + n) = make_float2(acc[mt][nt][2], acc[mt][nt][3]);
        }
    }
}

// ------------------- per-phase scalar work -----------------------------------------
__device__ void cell_work(int bid, const float* __restrict__ b_ih,
                          const float* __restrict__ b_hh) {
    int id = bid * 256 + threadIdx.x;           // 0..32767
    int m = id >> 10, d = id & 1023;
    float ig = b_ih[d]        + b_hh[d];
    float fg = b_ih[1024 + d] + b_hh[1024 + d];
    float gg = b_ih[2048 + d] + b_hh[2048 + d];
    float og = b_ih[3072 + d] + b_hh[3072 + d];
#pragma unroll
    for (int s = 0; s < 4; s++) {
        const float* p0 = g_gatesp2 + (size_t)(s * 64 + m) * 4096;
        const float* p1 = g_gatesp2 + (size_t)(s * 64 + 32 + m) * 4096;
        ig += __ldcg(p0 + d)        + __ldcg(p1 + d);
        fg += __ldcg(p0 + 1024 + d) + __ldcg(p1 + 1024 + d);
        gg += __ldcg(p0 + 2048 + d) + __ldcg(p1 + 2048 + d);
        og += __ldcg(p0 + 3072 + d) + __ldcg(p1 + 3072 + d);
    }
    float si = 1.f / (1.f + expf(-ig));
    float sf = 1.f / (1.f + expf(-fg));
    float so = 1.f / (1.f + expf(-og));
    float c = sf * __ldcg(&g_c[id]) + si * tanhf(gg);
    g_c[id] = c;
    float h = so * tanhf(c);
    __nv_bfloat16 hh, hl; split_bf(h, hh, hl);
    // hproj A2 [64][2048]
    g_A2h[m * 2048 + d] = hh;
    g_A2h[m * 2048 + 1024 + d] = hh;
    g_A2h[(32 + m) * 2048 + d] = hl;
    // pre A2 [64][6144]
    g_A2p[m * 6144 + d] = hh;
    g_A2p[m * 6144 + 3072 + d] = hh;
    g_A2p[(32 + m) * 6144 + d] = hl;
    // gates A2 [64][8192]: h at ks 3072..4096
    g_A2g[m * 8192 + 3072 + d] = hh;
    g_A2g[m * 8192 + 7168 + d] = hh;
    g_A2g[(32 + m) * 8192 + 3072 + d] = hl;
}

__device__ void pretanh_work(int t, int bid) {
    int id = bid * 256 + threadIdx.x;           // 0..32767
    int m = id >> 10, d = id & 1023;
    float v = 0.f;
#pragma unroll
    for (int s = 0; s < 16; s++) {
        v += __ldcg(&g_prep2[(size_t)(s * 64 + m) * 1024 + d]);
        v += __ldcg(&g_prep2[(size_t)(s * 64 + 32 + m) * 1024 + d]);
    }
    v = tanhf(v);
    int row = t * B + m;
    __nv_bfloat16 hi, lo; split_bf(v, hi, lo);
    __nv_bfloat16* arow = g_Abf + (size_t)row * KP;
    arow[d] = hi; arow[1024 + d] = lo; arow[2048 + d] = hi;
}

__device__ void attn_work(int b, float* s_hp, float* s_wl,
                          const float* __restrict__ x_enc,
                          const float* __restrict__ x_enc_k,
                          const unsigned char* __restrict__ xm,
                          const float* __restrict__ w_trg_b,
                          const float* __restrict__ w_att,
                          const float* __restrict__ w_att_b) {
    int tid = threadIdx.x;
    int lane = tid & 31, wd = tid >> 5;
    for (int d = tid; d < 1024; d += 256) {
        float sum = w_trg_b[d];
#pragma unroll
        for (int s = 0; s < 16; s++) {
            sum += __ldcg(&g_hprojp2[(size_t)(s * 64 + b) * 1024 + d]);
            sum += __ldcg(&g_hprojp2[(size_t)(s * 64 + 32 + b) * 1024 + d]);
        }
        s_hp[d] = sum;
    }
    __syncthreads();
    for (int l = wd; l < LX; l += 8) {
        const float* xk = x_enc_k + ((size_t)b * LX + l) * D;
        float s = 0.f;
#pragma unroll 8
        for (int i = 0; i < 32; i++) {
            int d = lane + i * 32;
            s += fast_tanh(xk[d] + s_hp[d]) * w_att[d];
        }
#pragma unroll
        for (int off = 16; off; off >>= 1) s += __shfl_xor_sync(0xffffffffu, s, off);
        if (lane == 0) {
            float tot = s + w_att_b[0];
            if (xm[b * LX + l]) tot = -1e9f;
            s_wl[l] = tot;
        }
    }
    __syncthreads();
    if (tid == 0) {
        float mx = -1e30f;
        for (int l = 0; l < LX; l++) mx = fmaxf(mx, s_wl[l]);
        float z = 0.f;
        for (int l = 0; l < LX; l++) { float e = expf(s_wl[l] - mx); s_wl[l] = e; z += e; }
        float inv = 1.f / z;
        for (int l = 0; l < LX; l++) s_wl[l] *= inv;
    }
    __syncthreads();
    {
        int d2 = tid * 8;
        const float* xe = x_enc + (size_t)b * LX * 2048 + d2;
        float f[8];
#pragma unroll
        for (int q = 0; q < 8; q++) f[q] = 0.f;
#pragma unroll 8
        for (int l = 0; l < LX; l++) {
            float w = s_wl[l];
            float4 x0 = *(const float4*)(xe + (size_t)l * 2048);
            float4 x1 = *(const float4*)(xe + (size_t)l * 2048 + 4);
            f[0] += w * x0.x; f[1] += w * x0.y; f[2] += w * x0.z; f[3] += w * x0.w;
            f[4] += w * x1.x; f[5] += w * x1.y; f[6] += w * x1.z; f[7] += w * x1.w;
        }
#pragma unroll
        for (int q = 0; q < 8; q++) {
            int dd = 1024 + d2 + q;             // ks position of feed
            __nv_bfloat16 hi, lo; split_bf(f[q], hi, lo);
            g_A2p[b * 6144 + dd] = hi;
            g_A2p[b * 6144 + 3072 + dd] = hi;
            g_A2p[(32 + b) * 6144 + dd] = lo;
            g_A2g[b * 8192 + dd] = hi;
            g_A2g[b * 8192 + 4096 + dd] = hi;
            g_A2g[(32 + b) * 8192 + dd] = lo;
        }
    }
}

__device__ void emb_prefetch(int b, int tnext, const float* __restrict__ word_emb,
                             const int* __restrict__ y_train) {
    int d = threadIdx.x * 4;
    int y = y_train[b * TT + tnext];
    float4 v = *(const float4*)(word_emb + (size_t)y * D + d);
    float vv[4] = {v.x, v.y, v.z, v.w};
#pragma unroll
    for (int q = 0; q < 4; q++) {
        __nv_bfloat16 hi, lo; split_bf(vv[q], hi, lo);
        int k = d + q;
        g_A2g[b * 8192 + k] = hi;
        g_A2g[b * 8192 + 4096 + k] = hi;
        g_A2g[(32 + b) * 8192 + k] = lo;
    }
}

// ------------------- persistent step kernel ----------------------------------------
__global__ void __launch_bounds__(256, 1) k_steps(
    const float* __restrict__ x_enc, const float* __restrict__ x_enc_k,
    const unsigned char* __restrict__ xm, const int* __restrict__ y_train,
    const float* __restrict__ word_emb,
    const float* __restrict__ b_ih, const float* __restrict__ b_hh,
    const float* __restrict__ w_trg_b, const float* __restrict__ w_att,
    const float* __restrict__ w_att_b) {
    __shared__ __align__(16) char s_raw[46080];
    uint32_t sb = smem_u32(s_raw);
    float* s_hp = (float*)s_raw;            // attn overlay (phase 4 only)
    float* s_wl = (float*)(s_raw + 4096);
    int bid = blockIdx.x;
    unsigned gen = 0;

    for (int t = 0; t < TT; t++) {
        // phase 1: pretanh(t-1) + gates MMA
        if (t > 0) pretanh_work(t - 1, bid);
        mma_phase3(sb, g_A2g, g_Wg2, g_gatesp2, 4096, 8192, 64,
                   (bid & 31) * 128, bid >> 5);
        gridbar(++gen);
        // phase 2: LSTM cell (+ writes h2 into all A2 buffers)
        cell_work(bid, b_ih, b_hh);
        gridbar(++gen);
        // phase 3: hproj MMA
        mma_phase3(sb, g_A2h, g_Wh2, g_hprojp2, 1024, 2048, 4,
                   (bid & 7) * 128, bid >> 3);
        gridbar(++gen);
        // phase 4: attention (CTAs 0-31) + emb(t+1) prefetch (CTAs 32-63)
        if (bid < 32)
            attn_work(bid, s_hp, s_wl, x_enc, x_enc_k, xm, w_trg_b, w_att, w_att_b);
        else if (bid < 64 && t + 1 < TT)
            emb_prefetch(bid - 32, t + 1, word_emb, y_train);
        gridbar(++gen);
        // phase 5: pre MMA
        mma_phase3(sb, g_A2p, g_Wp2, g_prep2, 1024, 6144, 12,
                   (bid & 7) * 128, bid >> 3);
        gridbar(++gen);
    }
    pretanh_work(TT - 1, bid);
}

// ------------------- logits GEMM via mma.sync (unchanged, passing) ------------------
__global__ void __launch_bounds__(256, 2) k_logits_mma(float* __restrict__ out) {
    __shared__ __align__(16) __nv_bfloat16 sA[2][128][40];
    __shared__ __align__(16) __nv_bfloat16 sB[2][128][40];
    int tid = threadIdx.x;
    int lane = tid & 31, wid = tid >> 5;
    int warpM = wid & 1, warpN = wid >> 1;
    int row0 = blockIdx.x * 128;
    int col0 = blockIdx.y * 128;

    int a_row = (lane & 7) + ((lane >> 3) & 1) * 8;
    int a_k   = (lane >> 4) * 8;
    int b_row = (lane & 7) + (lane >> 4) * 8;
    int b_k   = ((lane >> 3) & 1) * 8;
    uint32_t aBase = smem_u32(&sA[0][0][0]) + (warpM * 64 + a_row) * 80 + a_k * 2;
    uint32_t bBase = smem_u32(&sB[0][0][0]) + (warpN * 32 + b_row) * 80 + b_k * 2;

    int ldr = tid >> 2;
    int ldi = tid & 3;

    float acc[4][4][4];
#pragma unroll
    for (int i = 0; i < 4; i++)
#pragma unroll
        for (int j = 0; j < 4; j++)
#pragma unroll
            for (int q = 0; q < 4; q++) acc[i][j][q] = 0.f;

#pragma unroll
    for (int q = 0; q < 2; q++) {
        int r = ldr + q * 64;
        cpasync16(smem_u32(&sA[0][r][ldi * 8]), g_Abf + (size_t)(row0 + r) * KP + ldi * 8);
        cpasync16(smem_u32(&sB[0][r][ldi * 8]), g_Bbf + (size_t)(col0 + r) * KP + ldi * 8);
    }
    asm volatile("cp.async.commit_group;" ::: "memory");

    const int NCH = KP / 32;
    for (int i = 0; i < NCH; i++) {
        int st = i & 1;
        if (i + 1 < NCH) {
            int ns = st ^ 1;
            int kb = (i + 1) * 32;
#pragma unroll
            for (int q = 0; q < 2; q++) {
                int r = ldr + q * 64;
                cpasync16(smem_u32(&sA[ns][r][ldi * 8]),
                          g_Abf + (size_t)(row0 + r) * KP + kb + ldi * 8);
                cpasync16(smem_u32(&sB[ns][r][ldi * 8]),
                          g_Bbf + (size_t)(col0 + r) * KP + kb + ldi * 8);
            }
            asm volatile("cp.async.commit_group;" ::: "memory");
            asm volatile("cp.async.wait_group 1;" ::: "memory");
        } else {
            asm volatile("cp.async.wait_group 0;" ::: "memory");
        }
        __syncthreads();

        uint32_t stoff = st * (uint32_t)(128 * 80);
#pragma unroll
        for (int k16 = 0; k16 < 2; k16++) {
            uint32_t koff = stoff + k16 * 32;
            uint32_t a[4][4], b[2][4];
#pragma unroll
            for (int mt = 0; mt < 4; mt++) ldm_x4(a[mt], aBase + koff + mt * 1280);
#pragma unroll
            for (int p = 0; p < 2; p++)    ldm_x4(b[p], bBase + koff + p * 1280);
#pragma unroll
            for (int mt = 0; mt < 4; mt++)
#pragma unroll
                for (int nt = 0; nt < 4; nt++)
                    mma_bf16(acc[mt][nt], a[mt], &b[nt >> 1][(nt & 1) * 2]);
        }
        __syncthreads();
    }

    int grp = lane >> 2, tig = lane & 3;
#pragma unroll
    for (int mt = 0; mt < 4; mt++) {
        int m1 = row0 + warpM * 64 + mt * 16 + grp;
        int m2 = m1 + 8;
        float* o1 = out + ((size_t)(m1 & 31) * TT + (m1 >> 5)) * V;
        float* o2 = out + ((size_t)(m2 & 31) * TT + (m2 >> 5)) * V;
#pragma unroll
        for (int nt = 0; nt < 4; nt++) {
            int n = col0 + warpN * 32 + nt * 8 + tig * 2;
            *(float2*)(o1 + n) = make_float2(acc[mt][nt][0], acc[mt][nt][1]);
            *(float2*)(o2 + n) = make_float2(acc[mt][nt][2], acc[mt][nt][3]);
        }
    }
}

// ------------------- launch ----------------------------------------------------------
extern "C" void kernel_launch(void* const* d_in, const int* in_sizes, int n_in,
                              void* d_out, int out_size) {
    const float* x_enc      = (const float*)d_in[0];
    const float* x_enc_k    = (const float*)d_in[1];
    const float* h0         = (const float*)d_in[2];
    const float* c0         = (const float*)d_in[3];
    const unsigned char* xm = (const unsigned char*)d_in[4];
    const int*   y_train    = (const int*)d_in[5];
    const float* word_emb   = (const float*)d_in[6];
    const float* W_ih       = (const float*)d_in[7];
    const float* W_hh       = (const float*)d_in[8];
    const float* b_ih       = (const float*)d_in[9];
    const float* b_hh       = (const float*)d_in[10];
    const float* w_trg_W    = (const float*)d_in[11];
    const float* w_trg_b    = (const float*)d_in[12];
    const float* w_att      = (const float*)d_in[13];
    const float* w_att_b    = (const float*)d_in[14];
    const float* ctx_W      = (const float*)d_in[15];
    const float* RW         = (const float*)d_in[16];
    float* out = (float*)d_out;

    k_convB<<<(V * D) / 256, 256>>>(RW);
    k_convWg<<<dim3(16, 4096), 256>>>(W_ih, W_hh);
    k_convWh<<<dim3(4, 1024), 256>>>(w_trg_W);
    k_convWp<<<dim3(12, 1024), 256>>>(ctx_W);
    // init covers A2g full + A2h/A2p zero blocks + c0: 64*8192 + 32*1024 + 32*3072 + 32*1024
    int init_total = 64 * 8192 + 32 * 1024 + 32 * 3072 + B * D;
    k_init0<<<(init_total + 255) / 256, 256>>>(h0, c0, word_emb, y_train);
    k_steps<<<GRIDN, 256>>>(x_enc, x_enc_k, xm, y_train, word_emb,
                            b_ih, b_hh, w_trg_b, w_att, w_att_b);
    k_logits_mma<<<dim3((B * TT) / 128, V / 128), 256>>>(out);
}